// round 1
// baseline (speedup 1.0000x reference)
#include <cuda_runtime.h>

#define NB 2
#define NT 2048
#define ND 1024
#define NH 16
#define NDH 64

// Scratch (allocation-free rule: __device__ globals)
__device__ float g_q[NB*NH*NT*NDH];     // [b,h,t,dh]
__device__ float g_k[NB*NH*NT*NDH];
__device__ float g_v[NB*NH*NT*NDH];
__device__ float g_att[NB*NT*ND];       // [b,t,d]

// ---------------------------------------------------------------------------
// Tiled fp32 GEMM: C[M=4096, N=1024] = X @ W + bias
// MODE 0: z in {0,1,2} selects (Wq,bq)->g_q, (Wk,bk)->g_k, (Wv,bv)->g_v,
//         epilogue scatters into [b,h,t,dh] layout.
// MODE 1: X := g_att, writes OutP in [b,t,d] (row-major M x N).
// 128x128 tile, BK=8, 256 threads, 8x8 microtile, register prefetch.
// ---------------------------------------------------------------------------
template<int MODE>
__global__ __launch_bounds__(256)
void sgemm_kernel(const float* __restrict__ X,
                  const float* __restrict__ Wa, const float* __restrict__ Wb,
                  const float* __restrict__ Wc,
                  const float* __restrict__ ba, const float* __restrict__ bb,
                  const float* __restrict__ bc,
                  float* __restrict__ OutP)
{
    __shared__ __align__(16) float As[8][128];   // [k][m] (transposed)
    __shared__ __align__(16) float Bs[8][128];   // [k][n]

    const float* W    = Wa;
    const float* bias = ba;
    float*       dst0 = g_q;
    if (MODE == 0) {
        if (blockIdx.z == 1) { W = Wb; bias = bb; dst0 = g_k; }
        else if (blockIdx.z == 2) { W = Wc; bias = bc; dst0 = g_v; }
    }
    const float* Xb = (MODE == 0) ? X : g_att;

    const int tid = threadIdx.x;
    const int tx = tid & 15, ty = tid >> 4;
    const int m0 = blockIdx.y * 128, n0 = blockIdx.x * 128;

    const int lam = tid >> 1,  lak = (tid & 1) * 4;   // A tile load map
    const int lbk = tid >> 5,  lbn = (tid & 31) * 4;  // B tile load map

    const float* Xp = Xb + (m0 + lam) * ND + lak;
    const float* Wp = W + lbk * ND + n0 + lbn;

    float4 ar = *(const float4*)Xp;
    float4 br = *(const float4*)Wp;

    float acc[8][8];
    #pragma unroll
    for (int r = 0; r < 8; r++)
        #pragma unroll
        for (int c = 0; c < 8; c++) acc[r][c] = 0.f;

    for (int k0 = 0; k0 < ND; k0 += 8) {
        __syncthreads();
        As[lak+0][lam] = ar.x; As[lak+1][lam] = ar.y;
        As[lak+2][lam] = ar.z; As[lak+3][lam] = ar.w;
        *(float4*)&Bs[lbk][lbn] = br;
        __syncthreads();
        if (k0 + 8 < ND) {                       // prefetch next K-slab
            ar = *(const float4*)(Xp + (k0 + 8));
            br = *(const float4*)(Wp + (k0 + 8) * ND);
        }
        #pragma unroll
        for (int kk = 0; kk < 8; kk++) {
            float a[8], b[8];
            *(float4*)(a)     = *(const float4*)&As[kk][ty*8];
            *(float4*)(a + 4) = *(const float4*)&As[kk][ty*8 + 4];
            *(float4*)(b)     = *(const float4*)&Bs[kk][tx*8];
            *(float4*)(b + 4) = *(const float4*)&Bs[kk][tx*8 + 4];
            #pragma unroll
            for (int r = 0; r < 8; r++)
                #pragma unroll
                for (int c = 0; c < 8; c++)
                    acc[r][c] = fmaf(a[r], b[c], acc[r][c]);
        }
    }

    #pragma unroll
    for (int r = 0; r < 8; r++) {
        int m  = m0 + ty*8 + r;
        int bi = m >> 11;          // m / NT (NT = 2048)
        int t  = m & (NT - 1);
        #pragma unroll
        for (int c = 0; c < 8; c++) {
            int n = n0 + tx*8 + c;
            float v = acc[r][c] + bias[n];
            if (MODE == 0) {
                int h = n >> 6, j = n & 63;
                dst0[(((bi*NH + h)*NT + t) << 6) + j] = v;
            } else {
                OutP[m*ND + n] = v;
            }
        }
    }
}

// ---------------------------------------------------------------------------
// RoPE (in-place on g_q, g_k). Each thread handles the pair (j, j+32), j<32.
// out[j]    = u[j]*cos_j    - u[j+32]*sin_j         (freq index j/2)
// out[j+32] = u[j+32]*cos_{j+32} + u[j]*sin_{j+32}  (freq index j/2 + 16)
// Double-precision trig: sin(t * invfreq) with t up to 2047 amplifies
// inv-freq rounding ~2048x; keeps us comfortably under the 1e-3 tolerance.
// ---------------------------------------------------------------------------
__global__ void rope_kernel()
{
    const int total = NB*NH*NT*32;
    int idx = blockIdx.x * blockDim.x + threadIdx.x;
    if (idx >= total) return;
    int j    = idx & 31;
    int bt   = idx >> 5;            // bh*NT + t
    int t    = bt & (NT - 1);
    int base = bt * 64;

    const double LN1E4 = 9.210340371976184;
    double e1 = (double)(j & ~1) / 64.0;
    double e2 = (double)((j & ~1) + 32) / 64.0;
    double a1 = (double)t * exp(-e1 * LN1E4);
    double a2 = (double)t * exp(-e2 * LN1E4);
    float c1 = (float)cos(a1), s1 = (float)sin(a1);
    float c2 = (float)cos(a2), s2 = (float)sin(a2);

    float q1 = g_q[base + j], q2 = g_q[base + j + 32];
    g_q[base + j]      = q1*c1 - q2*s1;
    g_q[base + j + 32] = q2*c2 + q1*s2;
    float k1 = g_k[base + j], k2 = g_k[base + j + 32];
    g_k[base + j]      = k1*c1 - k2*s1;
    g_k[base + j + 32] = k2*c2 + k1*s2;
}

// ---------------------------------------------------------------------------
// Flash attention, fp32, causal. One block = 64 queries of one (b,h).
// 256 threads as 16x16, each owns a 4x4 microtile.
// Smem layouts picked for conflict-free inner-loop LDS.128:
//   Qt[d][i], Kt[d][j] (transposed, stride 68), Ps[j][i] (stride 68),
//   Vs[j][c] (natural, stride 64).
// ---------------------------------------------------------------------------
__global__ __launch_bounds__(256)
void attn_kernel()
{
    extern __shared__ __align__(16) float sm[];
    float* Qt = sm;                  // 64*68
    float* Kt = sm + 64*68;          // 64*68
    float* Ps = sm + 2*64*68;        // 64*68
    float* Vs = sm + 3*64*68;        // 64*64

    const int tid = threadIdx.x;
    const int tx = tid & 15, ty = tid >> 4;
    const int bh = blockIdx.y;
    const int qb = blockIdx.x * 64;

    const float* Qg = g_q + (bh*NT + qb) * 64;
    const float* Kg = g_k + bh*NT*64;
    const float* Vg = g_v + bh*NT*64;

    // Load Q tile, transposed into Qt[d][i]
    #pragma unroll
    for (int l = 0; l < 4; l++) {
        int e = (l*256 + tid) * 4;
        int i = e >> 6, d = e & 63;
        float4 v4 = *(const float4*)(Qg + i*64 + d);
        Qt[(d+0)*68 + i] = v4.x; Qt[(d+1)*68 + i] = v4.y;
        Qt[(d+2)*68 + i] = v4.z; Qt[(d+3)*68 + i] = v4.w;
    }

    const int i0 = ty * 4;   // query rows owned
    const int c0 = tx * 4;   // key cols (S phase) / dh cols (PV phase)

    float m_old[4], l_sum[4], o[4][4];
    #pragma unroll
    for (int r = 0; r < 4; r++) {
        m_old[r] = -1e30f; l_sum[r] = 0.f;
        #pragma unroll
        for (int c = 0; c < 4; c++) o[r][c] = 0.f;
    }

    const int nkt = blockIdx.x + 1;      // causal: only tiles at/below diagonal
    for (int kt = 0; kt < nkt; kt++) {
        const float* Kgt = Kg + kt*64*64;
        const float* Vgt = Vg + kt*64*64;

        __syncthreads();   // prior PV reads of Ps/Vs done before overwrite
        #pragma unroll
        for (int l = 0; l < 4; l++) {
            int e = (l*256 + tid) * 4;
            int j = e >> 6, d = e & 63;
            float4 kv = *(const float4*)(Kgt + j*64 + d);
            Kt[(d+0)*68 + j] = kv.x; Kt[(d+1)*68 + j] = kv.y;
            Kt[(d+2)*68 + j] = kv.z; Kt[(d+3)*68 + j] = kv.w;
            float4 vv = *(const float4*)(Vgt + j*64 + d);
            *(float4*)(Vs + j*64 + d) = vv;
        }
        __syncthreads();

        // S = Q K^T (4x4 per thread)
        float s[4][4];
        #pragma unroll
        for (int r = 0; r < 4; r++)
            #pragma unroll
            for (int c = 0; c < 4; c++) s[r][c] = 0.f;
        #pragma unroll 16
        for (int d = 0; d < 64; d++) {
            float4 aq = *(const float4*)(Qt + d*68 + i0);
            float4 ak = *(const float4*)(Kt + d*68 + c0);
            float a_[4] = {aq.x, aq.y, aq.z, aq.w};
            float b_[4] = {ak.x, ak.y, ak.z, ak.w};
            #pragma unroll
            for (int r = 0; r < 4; r++)
                #pragma unroll
                for (int c = 0; c < 4; c++)
                    s[r][c] = fmaf(a_[r], b_[c], s[r][c]);
        }

        const bool ondiag = (kt == blockIdx.x);
        #pragma unroll
        for (int r = 0; r < 4; r++)
            #pragma unroll
            for (int c = 0; c < 4; c++) {
                float sv = s[r][c] * 0.125f;              // 1/sqrt(64)
                if (ondiag && (c0 + c > i0 + r)) sv = -1e30f;
                s[r][c] = sv;
            }

        // Online softmax per row; row group = 16 lanes sharing ty
        #pragma unroll
        for (int r = 0; r < 4; r++) {
            float mr = fmaxf(fmaxf(s[r][0], s[r][1]), fmaxf(s[r][2], s[r][3]));
            #pragma unroll
            for (int off = 8; off > 0; off >>= 1)
                mr = fmaxf(mr, __shfl_xor_sync(0xffffffffu, mr, off));
            float mn = fmaxf(m_old[r], mr);
            float rs = 0.f;
            #pragma unroll
            for (int c = 0; c < 4; c++) {
                float p = __expf(s[r][c] - mn);
                s[r][c] = p; rs += p;
            }
            #pragma unroll
            for (int off = 8; off > 0; off >>= 1)
                rs += __shfl_xor_sync(0xffffffffu, rs, off);
            float al = __expf(m_old[r] - mn);
            l_sum[r] = l_sum[r]*al + rs;
            m_old[r] = mn;
            #pragma unroll
            for (int c = 0; c < 4; c++) o[r][c] *= al;
            #pragma unroll
            for (int c = 0; c < 4; c++)
                Ps[(c0 + c)*68 + (i0 + r)] = s[r][c];      // transposed store
        }
        __syncthreads();   // Ps visible to all

        // O += P V  (4x4 per thread over (qrow, dh))
        #pragma unroll 16
        for (int jj = 0; jj < 64; jj++) {
            float4 pp = *(const float4*)(Ps + jj*68 + i0);
            float4 vv = *(const float4*)(Vs + jj*64 + c0);
            float a_[4] = {pp.x, pp.y, pp.z, pp.w};
            float b_[4] = {vv.x, vv.y, vv.z, vv.w};
            #pragma unroll
            for (int r = 0; r < 4; r++)
                #pragma unroll
                for (int c = 0; c < 4; c++)
                    o[r][c] = fmaf(a_[r], b_[c], o[r][c]);
        }
    }

    // Write normalized output to [b,t,d] layout
    const int bi = bh / NH, h = bh % NH;
    #pragma unroll
    for (int r = 0; r < 4; r++) {
        float inv = 1.f / l_sum[r];
        int t = qb + i0 + r;
        #pragma unroll
        for (int c = 0; c < 4; c++)
            g_att[(bi*NT + t)*ND + h*64 + c0 + c] = o[r][c] * inv;
    }
}

// ---------------------------------------------------------------------------
// Launch. Inputs (metadata order): x, mask, wq, bq, wk, bk, wv, bv, wo, bo.
// mask is the causal mask -> known analytically, unused.
// ---------------------------------------------------------------------------
extern "C" void kernel_launch(void* const* d_in, const int* in_sizes, int n_in,
                              void* d_out, int out_size)
{
    const float* x  = (const float*)d_in[0];
    const float* wq = (const float*)d_in[2];
    const float* bq = (const float*)d_in[3];
    const float* wk = (const float*)d_in[4];
    const float* bk = (const float*)d_in[5];
    const float* wv = (const float*)d_in[6];
    const float* bv = (const float*)d_in[7];
    const float* wo = (const float*)d_in[8];
    const float* bo = (const float*)d_in[9];
    float* out = (float*)d_out;

    // 1) Fused QKV projections (z = 0,1,2) -> g_q/g_k/g_v in [b,h,t,dh]
    dim3 gq(ND/128, (NB*NT)/128, 3);
    sgemm_kernel<0><<<gq, 256>>>(x, wq, wk, wv, bq, bk, bv, nullptr);

    // 2) RoPE in-place on Q, K
    rope_kernel<<<(NB*NH*NT*32)/256, 256>>>();

    // 3) Flash attention -> g_att in [b,t,d]
    int smem_bytes = (3*64*68 + 64*64) * (int)sizeof(float);   // 68608 B
    cudaFuncSetAttribute(attn_kernel,
                         cudaFuncAttributeMaxDynamicSharedMemorySize, smem_bytes);
    attn_kernel<<<dim3(NT/64, NB*NH), 256, smem_bytes>>>();

    // 4) Output projection -> d_out
    dim3 go(ND/128, (NB*NT)/128, 1);
    sgemm_kernel<1><<<go, 256>>>(x, wo, wo, wo, bo, bo, bo, out);
}

// round 4
// speedup vs baseline: 1.2322x; 1.2322x over previous
#include <cuda_runtime.h>
#include <cuda_bf16.h>
#include <cstdint>

#define NB 2
#define NT 2048
#define ND 1024
#define NH 16
#define NDH 64
#define MTOT (NB*NT)   // 4096

// ---------------------------------------------------------------------------
// Scratch (__device__ globals; allocation-free rule)
// ---------------------------------------------------------------------------
__device__ float g_q[NB*NH*NT*NDH];     // [b,h,t,dh]
__device__ float g_k[NB*NH*NT*NDH];
__device__ float g_v[NB*NH*NT*NDH];
__device__ float g_att[NB*NT*ND];       // [b,t,d]

__device__ __nv_bfloat16 g_xhi[MTOT*ND];          // split activations (reused for att)
__device__ __nv_bfloat16 g_xlo[MTOT*ND];
__device__ __nv_bfloat16 g_wthi[4*ND*ND];         // transposed split weights [z][n][k]
__device__ __nv_bfloat16 g_wtlo[4*ND*ND];

// ---------------------------------------------------------------------------
// PTX helpers: base-target-safe only (mma.sync sm_80+, cp.async sm_80+).
// NO tcgen05 — ptxas for this harness targets sm_103 (no 'a' features).
// ---------------------------------------------------------------------------
__device__ __forceinline__ uint32_t smem_u32(const void* p) {
    uint32_t a;
    asm("{ .reg .u64 t; cvta.to.shared.u64 t, %1; cvt.u32.u64 %0, t; }"
        : "=r"(a) : "l"(p));
    return a;
}
#define CP_ASYNC16(saddr, gptr) \
    asm volatile("cp.async.cg.shared.global [%0], [%1], 16;" \
                 :: "r"(saddr), "l"(gptr) : "memory")
#define CP_COMMIT() asm volatile("cp.async.commit_group;" ::: "memory")
template<int N>
__device__ __forceinline__ void cp_wait() {
    asm volatile("cp.async.wait_group %0;" :: "n"(N) : "memory");
}

__device__ __forceinline__ void mma16816(float* d,
        uint32_t a0, uint32_t a1, uint32_t a2, uint32_t a3,
        uint32_t b0, uint32_t b1) {
    asm volatile(
        "mma.sync.aligned.m16n8k16.row.col.f32.bf16.bf16.f32 "
        "{%0,%1,%2,%3}, {%4,%5,%6,%7}, {%8,%9}, {%0,%1,%2,%3};"
        : "+f"(d[0]), "+f"(d[1]), "+f"(d[2]), "+f"(d[3])
        : "r"(a0), "r"(a1), "r"(a2), "r"(a3), "r"(b0), "r"(b1));
}

__device__ __forceinline__ uint32_t lds32(const char* base, int elem) {
    return *(const uint32_t*)(base + elem * 2);
}

// ---------------------------------------------------------------------------
// Split fp32 -> bf16 hi/lo
// ---------------------------------------------------------------------------
__global__ void split_kernel(const float* __restrict__ src,
                             __nv_bfloat16* __restrict__ hi,
                             __nv_bfloat16* __restrict__ lo, int n)
{
    int i = blockIdx.x * blockDim.x + threadIdx.x;
    if (i < n) {
        float v = src[i];
        __nv_bfloat16 h = __float2bfloat16(v);
        hi[i] = h;
        lo[i] = __float2bfloat16(v - __bfloat162float(h));
    }
}

// ---------------------------------------------------------------------------
// Transpose + split all 4 weights: W[k][n] -> T[z][n][k] (hi/lo bf16)
// ---------------------------------------------------------------------------
__global__ void wsplit_kernel(const float* __restrict__ w0, const float* __restrict__ w1,
                              const float* __restrict__ w2, const float* __restrict__ w3)
{
    __shared__ float tile[32][33];
    int z = blockIdx.z;
    const float* W = (z == 0) ? w0 : (z == 1) ? w1 : (z == 2) ? w2 : w3;
    int k0 = blockIdx.y * 32, n0 = blockIdx.x * 32;
    int tx = threadIdx.x, ty = threadIdx.y;
    #pragma unroll
    for (int i = 0; i < 4; i++)
        tile[ty + i*8][tx] = W[(k0 + ty + i*8) * ND + n0 + tx];
    __syncthreads();
    #pragma unroll
    for (int i = 0; i < 4; i++) {
        float v = tile[tx][ty + i*8];
        __nv_bfloat16 h = __float2bfloat16(v);
        int idx = z*ND*ND + (n0 + ty + i*8) * ND + (k0 + tx);
        g_wthi[idx] = h;
        g_wtlo[idx] = __float2bfloat16(v - __bfloat162float(h));
    }
}

// ---------------------------------------------------------------------------
// HMMA split-bf16 GEMM: C[4096,1024] = X @ W + bias
// 128x128 CTA tile, BK=64, 8 warps (4x2), warp tile 32x64, double-buffered
// cp.async pipeline. 3 accumulating terms: hi*hi + hi*lo + lo*hi.
// MODE 0: z = blockIdx.z selects wq/wk/wv -> g_q/g_k/g_v in [b,h,t,dh]
// MODE 1: z = 3 (wo) -> OutP [b,t,d]
// ---------------------------------------------------------------------------
#define BK 64
#define STRIDE 72                      // bf16 elements per smem row (64 + 8 pad)
#define TILE_B (128*STRIDE*2)          // 18432 B per matrix tile
#define BUF_B  (4*TILE_B)              // Ahi, Alo, Bhi, Blo = 73728 B
#define SMEM_GEMM (2*BUF_B)            // 147456 B

template<int MODE>
__global__ __launch_bounds__(256)
void hmma_gemm(const __nv_bfloat16* __restrict__ Ahi_g,
               const __nv_bfloat16* __restrict__ Alo_g,
               const float* __restrict__ b0, const float* __restrict__ b1,
               const float* __restrict__ b2,
               float* __restrict__ OutP)
{
    extern __shared__ __align__(16) char smem[];
    const uint32_t sbase = smem_u32(smem);
    const int tid = threadIdx.x;
    const int wid = tid >> 5;
    const int lane = tid & 31;
    const int lq = lane >> 2;          // 0..7
    const int lr = lane & 3;           // 0..3

    const int z = (MODE == 0) ? blockIdx.z : 3;
    const __nv_bfloat16* Bhi_g = g_wthi + (size_t)z * ND * ND;
    const __nv_bfloat16* Blo_g = g_wtlo + (size_t)z * ND * ND;
    const float* bias = (MODE == 0) ? ((z == 0) ? b0 : (z == 1) ? b1 : b2) : b0;
    float* dst0 = (z == 0) ? g_q : (z == 1) ? g_k : g_v;

    const int m0 = blockIdx.y * 128, n0 = blockIdx.x * 128;
    const int wm = (wid >> 1) * 32;    // warp M offset in tile
    const int wn = (wid & 1) * 64;     // warp N offset in tile

    // --- loader mapping: thread t covers row t/2, half t&1 (64 B) per tile
    const int lrow = tid >> 1, lhalf = tid & 1;
    const __nv_bfloat16* gA_hi = Ahi_g + (size_t)(m0 + lrow) * ND + lhalf * 32;
    const __nv_bfloat16* gA_lo = Alo_g + (size_t)(m0 + lrow) * ND + lhalf * 32;
    const __nv_bfloat16* gB_hi = Bhi_g + (size_t)(n0 + lrow) * ND + lhalf * 32;
    const __nv_bfloat16* gB_lo = Blo_g + (size_t)(n0 + lrow) * ND + lhalf * 32;
    const uint32_t sldst = sbase + (lrow * STRIDE + lhalf * 32) * 2;

    float acc[2][8][4];
    #pragma unroll
    for (int mt = 0; mt < 2; mt++)
        #pragma unroll
        for (int nt = 0; nt < 8; nt++)
            #pragma unroll
            for (int i = 0; i < 4; i++) acc[mt][nt][i] = 0.f;

    auto issue = [&](int chunk, int buf) {
        const uint32_t s = sldst + buf * BUF_B;
        const int g = chunk * BK;
        #pragma unroll
        for (int i = 0; i < 4; i++) {
            CP_ASYNC16(s + 0*TILE_B + i*16, gA_hi + g + i*8);
            CP_ASYNC16(s + 1*TILE_B + i*16, gA_lo + g + i*8);
            CP_ASYNC16(s + 2*TILE_B + i*16, gB_hi + g + i*8);
            CP_ASYNC16(s + 3*TILE_B + i*16, gB_lo + g + i*8);
        }
        CP_COMMIT();
    };

    issue(0, 0);
    issue(1, 1);

    const int NCHUNK = ND / BK;        // 16
    for (int c = 0; c < NCHUNK; c++) {
        const int buf = c & 1;
        if (c < NCHUNK - 1) cp_wait<1>(); else cp_wait<0>();
        __syncthreads();

        const char* base = smem + buf * BUF_B;
        const char* sAh = base;
        const char* sAl = base + 1*TILE_B;
        const char* sBh = base + 2*TILE_B;
        const char* sBl = base + 3*TILE_B;

        #pragma unroll
        for (int ks = 0; ks < 4; ks++) {
            const int kc = ks * 16 + lr * 2;
            uint32_t ah[2][4], al[2][4];
            #pragma unroll
            for (int mt = 0; mt < 2; mt++) {
                const int r0 = wm + mt * 16 + lq;
                ah[mt][0] = lds32(sAh, r0*STRIDE + kc);
                ah[mt][1] = lds32(sAh, (r0+8)*STRIDE + kc);
                ah[mt][2] = lds32(sAh, r0*STRIDE + kc + 8);
                ah[mt][3] = lds32(sAh, (r0+8)*STRIDE + kc + 8);
                al[mt][0] = lds32(sAl, r0*STRIDE + kc);
                al[mt][1] = lds32(sAl, (r0+8)*STRIDE + kc);
                al[mt][2] = lds32(sAl, r0*STRIDE + kc + 8);
                al[mt][3] = lds32(sAl, (r0+8)*STRIDE + kc + 8);
            }
            #pragma unroll
            for (int nt = 0; nt < 8; nt++) {
                const int nr = wn + nt * 8 + lq;
                uint32_t bh0 = lds32(sBh, nr*STRIDE + kc);
                uint32_t bh1 = lds32(sBh, nr*STRIDE + kc + 8);
                uint32_t bl0 = lds32(sBl, nr*STRIDE + kc);
                uint32_t bl1 = lds32(sBl, nr*STRIDE + kc + 8);
                #pragma unroll
                for (int mt = 0; mt < 2; mt++) {
                    mma16816(acc[mt][nt], ah[mt][0], ah[mt][1], ah[mt][2], ah[mt][3], bh0, bh1);
                    mma16816(acc[mt][nt], ah[mt][0], ah[mt][1], ah[mt][2], ah[mt][3], bl0, bl1);
                    mma16816(acc[mt][nt], al[mt][0], al[mt][1], al[mt][2], al[mt][3], bh0, bh1);
                }
            }
        }
        __syncthreads();
        if (c + 2 < NCHUNK) issue(c + 2, buf);
    }

    // --- epilogue ---
    // D layout per mma: lane: c0=D[lq][lr*2], c1=D[lq][lr*2+1], c2/c3 = row lq+8
    const int nh0 = (n0 + wn) >> 6;    // head index (warp spans exactly one 64-col head)
    #pragma unroll
    for (int mt = 0; mt < 2; mt++) {
        #pragma unroll
        for (int nt = 0; nt < 8; nt++) {
            const int n = n0 + wn + nt * 8 + lr * 2;
            const float bx = bias[n], by = bias[n + 1];
            const int row0 = m0 + wm + mt * 16 + lq;
            #pragma unroll
            for (int half = 0; half < 2; half++) {
                const int m = row0 + half * 8;
                float2 v;
                v.x = acc[mt][nt][half*2 + 0] + bx;
                v.y = acc[mt][nt][half*2 + 1] + by;
                if (MODE == 0) {
                    const int bi = m >> 11, t = m & (NT - 1);
                    const int j = (n & 63);
                    *(float2*)&dst0[(((size_t)(bi*NH + nh0)*NT + t) << 6) + j] = v;
                } else {
                    *(float2*)&OutP[(size_t)m * ND + n] = v;
                }
            }
        }
    }
}

// ---------------------------------------------------------------------------
// RoPE (unchanged)
// ---------------------------------------------------------------------------
__global__ void rope_kernel()
{
    const int total = NB*NH*NT*32;
    int idx = blockIdx.x * blockDim.x + threadIdx.x;
    if (idx >= total) return;
    int j    = idx & 31;
    int bt   = idx >> 5;
    int t    = bt & (NT - 1);
    int base = bt * 64;

    const double LN1E4 = 9.210340371976184;
    double e1 = (double)(j & ~1) / 64.0;
    double e2 = (double)((j & ~1) + 32) / 64.0;
    double a1 = (double)t * exp(-e1 * LN1E4);
    double a2 = (double)t * exp(-e2 * LN1E4);
    float c1 = (float)cos(a1), s1 = (float)sin(a1);
    float c2 = (float)cos(a2), s2 = (float)sin(a2);

    float q1 = g_q[base + j], q2 = g_q[base + j + 32];
    g_q[base + j]      = q1*c1 - q2*s1;
    g_q[base + j + 32] = q2*c2 + q1*s2;
    float k1 = g_k[base + j], k2 = g_k[base + j + 32];
    g_k[base + j]      = k1*c1 - k2*s1;
    g_k[base + j + 32] = k2*c2 + k1*s2;
}

// ---------------------------------------------------------------------------
// Flash attention fp32 (unchanged from the passing R1 version)
// ---------------------------------------------------------------------------
__global__ __launch_bounds__(256)
void attn_kernel()
{
    extern __shared__ __align__(16) float sm[];
    float* Qt = sm;
    float* Kt = sm + 64*68;
    float* Ps = sm + 2*64*68;
    float* Vs = sm + 3*64*68;

    const int tid = threadIdx.x;
    const int tx = tid & 15, ty = tid >> 4;
    const int bh = blockIdx.y;
    const int qb = blockIdx.x * 64;

    const float* Qg = g_q + (bh*NT + qb) * 64;
    const float* Kg = g_k + bh*NT*64;
    const float* Vg = g_v + bh*NT*64;

    #pragma unroll
    for (int l = 0; l < 4; l++) {
        int e = (l*256 + tid) * 4;
        int i = e >> 6, d = e & 63;
        float4 v4 = *(const float4*)(Qg + i*64 + d);
        Qt[(d+0)*68 + i] = v4.x; Qt[(d+1)*68 + i] = v4.y;
        Qt[(d+2)*68 + i] = v4.z; Qt[(d+3)*68 + i] = v4.w;
    }

    const int i0 = ty * 4;
    const int c0 = tx * 4;

    float m_old[4], l_sum[4], o[4][4];
    #pragma unroll
    for (int r = 0; r < 4; r++) {
        m_old[r] = -1e30f; l_sum[r] = 0.f;
        #pragma unroll
        for (int c = 0; c < 4; c++) o[r][c] = 0.f;
    }

    const int nkt = blockIdx.x + 1;
    for (int kt = 0; kt < nkt; kt++) {
        const float* Kgt = Kg + kt*64*64;
        const float* Vgt = Vg + kt*64*64;

        __syncthreads();
        #pragma unroll
        for (int l = 0; l < 4; l++) {
            int e = (l*256 + tid) * 4;
            int j = e >> 6, d = e & 63;
            float4 kv = *(const float4*)(Kgt + j*64 + d);
            Kt[(d+0)*68 + j] = kv.x; Kt[(d+1)*68 + j] = kv.y;
            Kt[(d+2)*68 + j] = kv.z; Kt[(d+3)*68 + j] = kv.w;
            float4 vv = *(const float4*)(Vgt + j*64 + d);
            *(float4*)(Vs + j*64 + d) = vv;
        }
        __syncthreads();

        float s[4][4];
        #pragma unroll
        for (int r = 0; r < 4; r++)
            #pragma unroll
            for (int c = 0; c < 4; c++) s[r][c] = 0.f;
        #pragma unroll 16
        for (int d = 0; d < 64; d++) {
            float4 aq = *(const float4*)(Qt + d*68 + i0);
            float4 ak = *(const float4*)(Kt + d*68 + c0);
            float a_[4] = {aq.x, aq.y, aq.z, aq.w};
            float b_[4] = {ak.x, ak.y, ak.z, ak.w};
            #pragma unroll
            for (int r = 0; r < 4; r++)
                #pragma unroll
                for (int c = 0; c < 4; c++)
                    s[r][c] = fmaf(a_[r], b_[c], s[r][c]);
        }

        const bool ondiag = (kt == blockIdx.x);
        #pragma unroll
        for (int r = 0; r < 4; r++)
            #pragma unroll
            for (int c = 0; c < 4; c++) {
                float sv = s[r][c] * 0.125f;
                if (ondiag && (c0 + c > i0 + r)) sv = -1e30f;
                s[r][c] = sv;
            }

        #pragma unroll
        for (int r = 0; r < 4; r++) {
            float mr = fmaxf(fmaxf(s[r][0], s[r][1]), fmaxf(s[r][2], s[r][3]));
            #pragma unroll
            for (int off = 8; off > 0; off >>= 1)
                mr = fmaxf(mr, __shfl_xor_sync(0xffffffffu, mr, off));
            float mn = fmaxf(m_old[r], mr);
            float rs = 0.f;
            #pragma unroll
            for (int c = 0; c < 4; c++) {
                float p = __expf(s[r][c] - mn);
                s[r][c] = p; rs += p;
            }
            #pragma unroll
            for (int off = 8; off > 0; off >>= 1)
                rs += __shfl_xor_sync(0xffffffffu, rs, off);
            float al = __expf(m_old[r] - mn);
            l_sum[r] = l_sum[r]*al + rs;
            m_old[r] = mn;
            #pragma unroll
            for (int c = 0; c < 4; c++) o[r][c] *= al;
            #pragma unroll
            for (int c = 0; c < 4; c++)
                Ps[(c0 + c)*68 + (i0 + r)] = s[r][c];
        }
        __syncthreads();

        #pragma unroll 16
        for (int jj = 0; jj < 64; jj++) {
            float4 pp = *(const float4*)(Ps + jj*68 + i0);
            float4 vv = *(const float4*)(Vs + jj*64 + c0);
            float a_[4] = {pp.x, pp.y, pp.z, pp.w};
            float b_[4] = {vv.x, vv.y, vv.z, vv.w};
            #pragma unroll
            for (int r = 0; r < 4; r++)
                #pragma unroll
                for (int c = 0; c < 4; c++)
                    o[r][c] = fmaf(a_[r], b_[c], o[r][c]);
        }
    }

    const int bi = bh / NH, h = bh % NH;
    #pragma unroll
    for (int r = 0; r < 4; r++) {
        float inv = 1.f / l_sum[r];
        int t = qb + i0 + r;
        #pragma unroll
        for (int c = 0; c < 4; c++)
            g_att[(bi*NT + t)*ND + h*64 + c0 + c] = o[r][c] * inv;
    }
}

// ---------------------------------------------------------------------------
// Launch. Inputs: x, mask, wq, bq, wk, bk, wv, bv, wo, bo.
// ---------------------------------------------------------------------------
extern "C" void kernel_launch(void* const* d_in, const int* in_sizes, int n_in,
                              void* d_out, int out_size)
{
    const float* x  = (const float*)d_in[0];
    const float* wq = (const float*)d_in[2];
    const float* bq = (const float*)d_in[3];
    const float* wk = (const float*)d_in[4];
    const float* bk = (const float*)d_in[5];
    const float* wv = (const float*)d_in[6];
    const float* bv = (const float*)d_in[7];
    const float* wo = (const float*)d_in[8];
    const float* bo = (const float*)d_in[9];
    float* out = (float*)d_out;

    __nv_bfloat16 *xhi, *xlo; float* attp;
    cudaGetSymbolAddress((void**)&xhi, g_xhi);
    cudaGetSymbolAddress((void**)&xlo, g_xlo);
    cudaGetSymbolAddress((void**)&attp, g_att);

    cudaFuncSetAttribute(hmma_gemm<0>,
                         cudaFuncAttributeMaxDynamicSharedMemorySize, SMEM_GEMM);
    cudaFuncSetAttribute(hmma_gemm<1>,
                         cudaFuncAttributeMaxDynamicSharedMemorySize, SMEM_GEMM);

    // 1) split x; transpose+split all weights
    split_kernel<<<(MTOT*ND)/256, 256>>>(x, xhi, xlo, MTOT*ND);
    wsplit_kernel<<<dim3(32, 32, 4), dim3(32, 8)>>>(wq, wk, wv, wo);

    // 2) fused QKV projections (HMMA split-bf16) -> g_q/g_k/g_v [b,h,t,dh]
    hmma_gemm<0><<<dim3(8, 32, 3), 256, SMEM_GEMM>>>(xhi, xlo, bq, bk, bv, nullptr);

    // 3) RoPE in-place on Q, K
    rope_kernel<<<(NB*NH*NT*32)/256, 256>>>();

    // 4) Flash attention -> g_att [b,t,d]
    int smem_attn = (3*64*68 + 64*64) * (int)sizeof(float);
    cudaFuncSetAttribute(attn_kernel,
                         cudaFuncAttributeMaxDynamicSharedMemorySize, smem_attn);
    attn_kernel<<<dim3(NT/64, NB*NH), 256, smem_attn>>>();

    // 5) split attention output (reuse xhi/xlo), out-projection
    split_kernel<<<(MTOT*ND)/256, 256>>>(attp, xhi, xlo, MTOT*ND);
    hmma_gemm<1><<<dim3(8, 32, 1), 256, SMEM_GEMM>>>(xhi, xlo, bo, bo, bo, out);
}

// round 5
// speedup vs baseline: 2.6907x; 2.1836x over previous
#include <cuda_runtime.h>
#include <cuda_bf16.h>
#include <cstdint>

#define NB 2
#define NT 2048
#define ND 1024
#define NH 16
#define NDH 64
#define MTOT (NB*NT)   // 4096

// ---------------------------------------------------------------------------
// Scratch (__device__ globals; allocation-free rule)
// ---------------------------------------------------------------------------
__device__ float g_q[NB*NH*NT*NDH];     // [b,h,t,dh] fp32 (pre-rope, from gemm)
__device__ float g_k[NB*NH*NT*NDH];
__device__ float g_v[NB*NH*NT*NDH];
__device__ float g_att[NB*NT*ND];       // [b,t,d]

__device__ __nv_bfloat16 g_xhi[MTOT*ND];
__device__ __nv_bfloat16 g_xlo[MTOT*ND];
__device__ __nv_bfloat16 g_wthi[4*ND*ND];
__device__ __nv_bfloat16 g_wtlo[4*ND*ND];

// post-rope split operands for attention
__device__ __nv_bfloat16 g_qhi[NB*NH*NT*NDH];   // [b,h,t,dh]
__device__ __nv_bfloat16 g_qlo[NB*NH*NT*NDH];
__device__ __nv_bfloat16 g_khi[NB*NH*NT*NDH];
__device__ __nv_bfloat16 g_klo[NB*NH*NT*NDH];
__device__ __nv_bfloat16 g_vthi[NB*NH*NT*NDH];  // [b,h,dh,t]  (transposed)
__device__ __nv_bfloat16 g_vtlo[NB*NH*NT*NDH];

__device__ float4 g_rope[NT*32];                // (c1,s1,c2,s2) per (t,j)

// ---------------------------------------------------------------------------
// PTX helpers: base-target-safe (mma.sync / cp.async / ldmatrix; NO tcgen05)
// ---------------------------------------------------------------------------
__device__ __forceinline__ uint32_t smem_u32(const void* p) {
    uint32_t a;
    asm("{ .reg .u64 t; cvta.to.shared.u64 t, %1; cvt.u32.u64 %0, t; }"
        : "=r"(a) : "l"(p));
    return a;
}
#define CP_ASYNC16(saddr, gptr) \
    asm volatile("cp.async.cg.shared.global [%0], [%1], 16;" \
                 :: "r"(saddr), "l"(gptr) : "memory")
#define CP_COMMIT() asm volatile("cp.async.commit_group;" ::: "memory")
template<int N>
__device__ __forceinline__ void cp_wait() {
    asm volatile("cp.async.wait_group %0;" :: "n"(N) : "memory");
}
__device__ __forceinline__ void mma16816(float* d,
        uint32_t a0, uint32_t a1, uint32_t a2, uint32_t a3,
        uint32_t b0, uint32_t b1) {
    asm volatile(
        "mma.sync.aligned.m16n8k16.row.col.f32.bf16.bf16.f32 "
        "{%0,%1,%2,%3}, {%4,%5,%6,%7}, {%8,%9}, {%0,%1,%2,%3};"
        : "+f"(d[0]), "+f"(d[1]), "+f"(d[2]), "+f"(d[3])
        : "r"(a0), "r"(a1), "r"(a2), "r"(a3), "r"(b0), "r"(b1));
}
__device__ __forceinline__ void ldsm_x4(uint32_t& r0, uint32_t& r1,
                                        uint32_t& r2, uint32_t& r3, uint32_t addr) {
    asm volatile("ldmatrix.sync.aligned.m8n8.x4.shared.b16 {%0,%1,%2,%3}, [%4];"
                 : "=r"(r0), "=r"(r1), "=r"(r2), "=r"(r3) : "r"(addr));
}
__device__ __forceinline__ uint32_t lds32(const char* base, int elem) {
    return *(const uint32_t*)(base + elem * 2);
}
// pack two f32 -> bf16x2 (lo in bits [0:16))
__device__ __forceinline__ uint32_t packbf(float lo, float hi) {
    uint32_t d;
    asm("cvt.rn.bf16x2.f32 %0, %1, %2;" : "=r"(d) : "f"(hi), "f"(lo));
    return d;
}
__device__ __forceinline__ float bfx2_lo(uint32_t u) { return __uint_as_float(u << 16); }
__device__ __forceinline__ float bfx2_hi(uint32_t u) { return __uint_as_float(u & 0xffff0000u); }

#define SWZ128(o) ((o) ^ (((o) >> 3) & 0x70))

// ---------------------------------------------------------------------------
// Split fp32 -> bf16 hi/lo
// ---------------------------------------------------------------------------
__global__ void split_kernel(const float* __restrict__ src,
                             __nv_bfloat16* __restrict__ hi,
                             __nv_bfloat16* __restrict__ lo, int n)
{
    int i = blockIdx.x * blockDim.x + threadIdx.x;
    if (i < n) {
        float v = src[i];
        __nv_bfloat16 h = __float2bfloat16(v);
        hi[i] = h;
        lo[i] = __float2bfloat16(v - __bfloat162float(h));
    }
}

// ---------------------------------------------------------------------------
// Transpose + split all 4 weights: W[k][n] -> T[z][n][k] (hi/lo bf16)
// ---------------------------------------------------------------------------
__global__ void wsplit_kernel(const float* __restrict__ w0, const float* __restrict__ w1,
                              const float* __restrict__ w2, const float* __restrict__ w3)
{
    __shared__ float tile[32][33];
    int z = blockIdx.z;
    const float* W = (z == 0) ? w0 : (z == 1) ? w1 : (z == 2) ? w2 : w3;
    int k0 = blockIdx.y * 32, n0 = blockIdx.x * 32;
    int tx = threadIdx.x, ty = threadIdx.y;
    #pragma unroll
    for (int i = 0; i < 4; i++)
        tile[ty + i*8][tx] = W[(k0 + ty + i*8) * ND + n0 + tx];
    __syncthreads();
    #pragma unroll
    for (int i = 0; i < 4; i++) {
        float v = tile[tx][ty + i*8];
        __nv_bfloat16 h = __float2bfloat16(v);
        int idx = z*ND*ND + (n0 + ty + i*8) * ND + (k0 + tx);
        g_wthi[idx] = h;
        g_wtlo[idx] = __float2bfloat16(v - __bfloat162float(h));
    }
}

// ---------------------------------------------------------------------------
// HMMA split-bf16 GEMM (unchanged from R4, passing)
// ---------------------------------------------------------------------------
#define BK 64
#define STRIDE 72
#define TILE_B (128*STRIDE*2)
#define BUF_B  (4*TILE_B)
#define SMEM_GEMM (2*BUF_B)

template<int MODE>
__global__ __launch_bounds__(256)
void hmma_gemm(const __nv_bfloat16* __restrict__ Ahi_g,
               const __nv_bfloat16* __restrict__ Alo_g,
               const float* __restrict__ b0, const float* __restrict__ b1,
               const float* __restrict__ b2,
               float* __restrict__ OutP)
{
    extern __shared__ __align__(16) char smem[];
    const int tid = threadIdx.x;
    const int wid = tid >> 5;
    const int lane = tid & 31;
    const int lq = lane >> 2;
    const int lr = lane & 3;

    const int z = (MODE == 0) ? blockIdx.z : 3;
    const __nv_bfloat16* Bhi_g = g_wthi + (size_t)z * ND * ND;
    const __nv_bfloat16* Blo_g = g_wtlo + (size_t)z * ND * ND;
    const float* bias = (MODE == 0) ? ((z == 0) ? b0 : (z == 1) ? b1 : b2) : b0;
    float* dst0 = (z == 0) ? g_q : (z == 1) ? g_k : g_v;

    const int m0 = blockIdx.y * 128, n0 = blockIdx.x * 128;
    const int wm = (wid >> 1) * 32;
    const int wn = (wid & 1) * 64;

    const int lrow = tid >> 1, lhalf = tid & 1;
    const __nv_bfloat16* gA_hi = Ahi_g + (size_t)(m0 + lrow) * ND + lhalf * 32;
    const __nv_bfloat16* gA_lo = Alo_g + (size_t)(m0 + lrow) * ND + lhalf * 32;
    const __nv_bfloat16* gB_hi = Bhi_g + (size_t)(n0 + lrow) * ND + lhalf * 32;
    const __nv_bfloat16* gB_lo = Blo_g + (size_t)(n0 + lrow) * ND + lhalf * 32;
    const uint32_t sldst = smem_u32(smem) + (lrow * STRIDE + lhalf * 32) * 2;

    float acc[2][8][4];
    #pragma unroll
    for (int mt = 0; mt < 2; mt++)
        #pragma unroll
        for (int nt = 0; nt < 8; nt++)
            #pragma unroll
            for (int i = 0; i < 4; i++) acc[mt][nt][i] = 0.f;

    auto issue = [&](int chunk, int buf) {
        const uint32_t s = sldst + buf * BUF_B;
        const int g = chunk * BK;
        #pragma unroll
        for (int i = 0; i < 4; i++) {
            CP_ASYNC16(s + 0*TILE_B + i*16, gA_hi + g + i*8);
            CP_ASYNC16(s + 1*TILE_B + i*16, gA_lo + g + i*8);
            CP_ASYNC16(s + 2*TILE_B + i*16, gB_hi + g + i*8);
            CP_ASYNC16(s + 3*TILE_B + i*16, gB_lo + g + i*8);
        }
        CP_COMMIT();
    };

    issue(0, 0);
    issue(1, 1);

    const int NCHUNK = ND / BK;
    for (int c = 0; c < NCHUNK; c++) {
        const int buf = c & 1;
        if (c < NCHUNK - 1) cp_wait<1>(); else cp_wait<0>();
        __syncthreads();

        const char* base = smem + buf * BUF_B;
        const char* sAh = base;
        const char* sAl = base + 1*TILE_B;
        const char* sBh = base + 2*TILE_B;
        const char* sBl = base + 3*TILE_B;

        #pragma unroll
        for (int ks = 0; ks < 4; ks++) {
            const int kc = ks * 16 + lr * 2;
            uint32_t ah[2][4], al[2][4];
            #pragma unroll
            for (int mt = 0; mt < 2; mt++) {
                const int r0 = wm + mt * 16 + lq;
                ah[mt][0] = lds32(sAh, r0*STRIDE + kc);
                ah[mt][1] = lds32(sAh, (r0+8)*STRIDE + kc);
                ah[mt][2] = lds32(sAh, r0*STRIDE + kc + 8);
                ah[mt][3] = lds32(sAh, (r0+8)*STRIDE + kc + 8);
                al[mt][0] = lds32(sAl, r0*STRIDE + kc);
                al[mt][1] = lds32(sAl, (r0+8)*STRIDE + kc);
                al[mt][2] = lds32(sAl, r0*STRIDE + kc + 8);
                al[mt][3] = lds32(sAl, (r0+8)*STRIDE + kc + 8);
            }
            #pragma unroll
            for (int nt = 0; nt < 8; nt++) {
                const int nr = wn + nt * 8 + lq;
                uint32_t bh0 = lds32(sBh, nr*STRIDE + kc);
                uint32_t bh1 = lds32(sBh, nr*STRIDE + kc + 8);
                uint32_t bl0 = lds32(sBl, nr*STRIDE + kc);
                uint32_t bl1 = lds32(sBl, nr*STRIDE + kc + 8);
                #pragma unroll
                for (int mt = 0; mt < 2; mt++) {
                    mma16816(acc[mt][nt], ah[mt][0], ah[mt][1], ah[mt][2], ah[mt][3], bh0, bh1);
                    mma16816(acc[mt][nt], ah[mt][0], ah[mt][1], ah[mt][2], ah[mt][3], bl0, bl1);
                    mma16816(acc[mt][nt], al[mt][0], al[mt][1], al[mt][2], al[mt][3], bh0, bh1);
                }
            }
        }
        __syncthreads();
        if (c + 2 < NCHUNK) issue(c + 2, buf);
    }

    const int nh0 = (n0 + wn) >> 6;
    #pragma unroll
    for (int mt = 0; mt < 2; mt++) {
        #pragma unroll
        for (int nt = 0; nt < 8; nt++) {
            const int n = n0 + wn + nt * 8 + lr * 2;
            const float bx = bias[n], by = bias[n + 1];
            const int row0 = m0 + wm + mt * 16 + lq;
            #pragma unroll
            for (int half = 0; half < 2; half++) {
                const int m = row0 + half * 8;
                float2 v;
                v.x = acc[mt][nt][half*2 + 0] + bx;
                v.y = acc[mt][nt][half*2 + 1] + by;
                if (MODE == 0) {
                    const int bi = m >> 11, t = m & (NT - 1);
                    const int j = (n & 63);
                    *(float2*)&dst0[(((size_t)(bi*NH + nh0)*NT + t) << 6) + j] = v;
                } else {
                    *(float2*)&OutP[(size_t)m * ND + n] = v;
                }
            }
        }
    }
}

// ---------------------------------------------------------------------------
// RoPE: dp trig hoisted into a (t,j)-indexed table (65K evals, not 4.2M)
// ---------------------------------------------------------------------------
__global__ void rope_table()
{
    int idx = blockIdx.x * blockDim.x + threadIdx.x;
    if (idx >= NT*32) return;
    int t = idx >> 5, j = idx & 31;
    const double LN1E4 = 9.210340371976184;
    double e1 = (double)(j & ~1) / 64.0;
    double e2 = (double)((j & ~1) + 32) / 64.0;
    double a1 = (double)t * exp(-e1 * LN1E4);
    double a2 = (double)t * exp(-e2 * LN1E4);
    float4 r;
    r.x = (float)cos(a1); r.y = (float)sin(a1);
    r.z = (float)cos(a2); r.w = (float)sin(a2);
    g_rope[idx] = r;
}

// apply rope to Q,K (fp32) and emit split hi/lo bf16 operands for attention
__global__ void rope_apply()
{
    const int total = NB*NH*NT*32;
    int idx = blockIdx.x * blockDim.x + threadIdx.x;
    if (idx >= total) return;
    int j  = idx & 31;
    int bt = idx >> 5;
    int t  = bt & (NT - 1);
    size_t base = (size_t)bt * 64;

    float4 cs = g_rope[t*32 + j];
    float q1 = g_q[base + j], q2 = g_q[base + j + 32];
    float k1 = g_k[base + j], k2 = g_k[base + j + 32];
    float rq1 = q1*cs.x - q2*cs.y;
    float rq2 = q2*cs.z + q1*cs.w;
    float rk1 = k1*cs.x - k2*cs.y;
    float rk2 = k2*cs.z + k1*cs.w;

    __nv_bfloat16 h;
    h = __float2bfloat16(rq1); g_qhi[base+j]    = h; g_qlo[base+j]    = __float2bfloat16(rq1 - __bfloat162float(h));
    h = __float2bfloat16(rq2); g_qhi[base+j+32] = h; g_qlo[base+j+32] = __float2bfloat16(rq2 - __bfloat162float(h));
    h = __float2bfloat16(rk1); g_khi[base+j]    = h; g_klo[base+j]    = __float2bfloat16(rk1 - __bfloat162float(h));
    h = __float2bfloat16(rk2); g_khi[base+j+32] = h; g_klo[base+j+32] = __float2bfloat16(rk2 - __bfloat162float(h));
}

// ---------------------------------------------------------------------------
// V transpose + split: g_v [b,h,t,dh] fp32 -> g_vthi/lo [b,h,dh,t] bf16
// ---------------------------------------------------------------------------
__global__ __launch_bounds__(256) void vtrans()
{
    __shared__ float tile[64][65];
    const int bh = blockIdx.y, tb = blockIdx.x * 64;
    const int tid = threadIdx.x;
    const int r = tid >> 2, c4 = (tid & 3) * 16;
    const float* src = g_v + ((size_t)bh*NT + tb + r) * 64 + c4;
    #pragma unroll
    for (int i = 0; i < 4; i++) {
        float4 v = *(const float4*)(src + i*4);
        tile[r][c4+i*4+0] = v.x; tile[r][c4+i*4+1] = v.y;
        tile[r][c4+i*4+2] = v.z; tile[r][c4+i*4+3] = v.w;
    }
    __syncthreads();
    const int dh = tid >> 2, t4 = (tid & 3) * 16;
    size_t ob = ((size_t)bh*64 + dh) * NT + tb + t4;
    #pragma unroll
    for (int i = 0; i < 8; i++) {
        float a = tile[t4 + 2*i][dh], b = tile[t4 + 2*i + 1][dh];
        __nv_bfloat16 ha = __float2bfloat16(a), hb = __float2bfloat16(b);
        *(__nv_bfloat162*)(g_vthi + ob + 2*i) = __nv_bfloat162(ha, hb);
        __nv_bfloat16 la = __float2bfloat16(a - __bfloat162float(ha));
        __nv_bfloat16 lb = __float2bfloat16(b - __bfloat162float(hb));
        *(__nv_bfloat162*)(g_vtlo + ob + 2*i) = __nv_bfloat162(la, lb);
    }
}

// ---------------------------------------------------------------------------
// HMMA flash attention, split-bf16 3-term, causal.
// BM=128 (8 warps x 16 rows), BN=64 keys/tile, double-buffered cp.async smem.
// ---------------------------------------------------------------------------
#define AT_TILE_B 8192              // 64 rows x 128 B
#define AT_BUF_B  (4*AT_TILE_B)     // Khi,Klo,Vthi,Vtlo
#define SMEM_ATTN (2*AT_BUF_B)      // 65536

__global__ __launch_bounds__(256)
void attn_hmma()
{
    extern __shared__ __align__(128) char asmem[];
    const uint32_t sbase = smem_u32(asmem);
    const int tid = threadIdx.x, wid = tid >> 5, lane = tid & 31;
    const int lq = lane >> 2, lr = lane & 3;
    const int bx = gridDim.x - 1 - blockIdx.x;     // big-work CTAs first
    const int bh = blockIdx.y;
    const int qb = bx * 128;
    const int last = 2*bx + 1;

    const size_t hb = (size_t)bh * NT * 64;
    const __nv_bfloat16* Qh = g_qhi + hb;
    const __nv_bfloat16* Ql = g_qlo + hb;
    const __nv_bfloat16* Kh = g_khi + hb;
    const __nv_bfloat16* Kl = g_klo + hb;
    const __nv_bfloat16* Vh = g_vthi + hb;   // [dh][t]
    const __nv_bfloat16* Vl = g_vtlo + hb;

    // Q fragments (register-resident)
    uint32_t qh[4][4], ql[4][4];
    {
        const size_t r0 = (size_t)(qb + wid*16 + lq);
        #pragma unroll
        for (int kb = 0; kb < 4; kb++) {
            const int d0 = kb*16 + lr*2;
            qh[kb][0] = *(const uint32_t*)(Qh + r0*64 + d0);
            qh[kb][1] = *(const uint32_t*)(Qh + (r0+8)*64 + d0);
            qh[kb][2] = *(const uint32_t*)(Qh + r0*64 + d0 + 8);
            qh[kb][3] = *(const uint32_t*)(Qh + (r0+8)*64 + d0 + 8);
            ql[kb][0] = *(const uint32_t*)(Ql + r0*64 + d0);
            ql[kb][1] = *(const uint32_t*)(Ql + (r0+8)*64 + d0);
            ql[kb][2] = *(const uint32_t*)(Ql + r0*64 + d0 + 8);
            ql[kb][3] = *(const uint32_t*)(Ql + (r0+8)*64 + d0 + 8);
        }
    }

    float O[8][4];
    #pragma unroll
    for (int i = 0; i < 8; i++)
        #pragma unroll
        for (int c = 0; c < 4; c++) O[i][c] = 0.f;
    float m0 = -1e30f, m1 = -1e30f, l0 = 0.f, l1 = 0.f;

    const int lrow = tid >> 2;           // 0..63
    const int lcb  = (tid & 3) * 2;      // chunk base

    auto issue = [&](int kt, int buf) {
        const uint32_t sb = sbase + buf * AT_BUF_B;
        #pragma unroll
        for (int c2 = 0; c2 < 2; c2++) {
            const int c = lcb + c2;
            const uint32_t sw = SWZ128((uint32_t)(lrow*128 + c*16));
            const size_t gk = ((size_t)(kt*64 + lrow))*64 + c*8;
            const size_t gv = (size_t)lrow*NT + kt*64 + c*8;
            CP_ASYNC16(sb + 0*AT_TILE_B + sw, Kh + gk);
            CP_ASYNC16(sb + 1*AT_TILE_B + sw, Kl + gk);
            CP_ASYNC16(sb + 2*AT_TILE_B + sw, Vh + gv);
            CP_ASYNC16(sb + 3*AT_TILE_B + sw, Vl + gv);
        }
        CP_COMMIT();
    };

    issue(0, 0);
    const int rg0 = qb + wid*16 + lq;    // first owned row; second is rg0+8
    const int trow = lane & 7;
    const int tcol = (lane >> 3) * 16;   // 16B column per 8x8 tile

    for (int kt = 0; kt <= last; kt++) {
        if (kt < last) issue(kt + 1, (kt + 1) & 1);
        if (kt < last) cp_wait<1>(); else cp_wait<0>();
        __syncthreads();

        const bool active = (kt*64 <= qb + wid*16 + 15);
        if (active) {
            const uint32_t sb = sbase + (kt & 1) * AT_BUF_B;
            const uint32_t off1 = SWZ128((uint32_t)(trow*128 + tcol));
            const uint32_t off2 = SWZ128((uint32_t)(trow*128 + 64 + tcol));

            // ---- S = Q K^T (3-term split) ----
            float S[8][4];
            #pragma unroll
            for (int nb = 0; nb < 8; nb++) {
                uint32_t ka[4], kb_[4], la[4], lb[4];
                const uint32_t ro = (uint32_t)(nb * 8 * 128);
                ldsm_x4(ka[0], ka[1], ka[2], ka[3], sb + 0*AT_TILE_B + ro + off1);
                ldsm_x4(kb_[0], kb_[1], kb_[2], kb_[3], sb + 0*AT_TILE_B + ro + off2);
                ldsm_x4(la[0], la[1], la[2], la[3], sb + 1*AT_TILE_B + ro + off1);
                ldsm_x4(lb[0], lb[1], lb[2], lb[3], sb + 1*AT_TILE_B + ro + off2);
                S[nb][0] = S[nb][1] = S[nb][2] = S[nb][3] = 0.f;
                mma16816(S[nb], qh[0][0], qh[0][1], qh[0][2], qh[0][3], ka[0], ka[1]);
                mma16816(S[nb], qh[1][0], qh[1][1], qh[1][2], qh[1][3], ka[2], ka[3]);
                mma16816(S[nb], qh[2][0], qh[2][1], qh[2][2], qh[2][3], kb_[0], kb_[1]);
                mma16816(S[nb], qh[3][0], qh[3][1], qh[3][2], qh[3][3], kb_[2], kb_[3]);
                mma16816(S[nb], qh[0][0], qh[0][1], qh[0][2], qh[0][3], la[0], la[1]);
                mma16816(S[nb], qh[1][0], qh[1][1], qh[1][2], qh[1][3], la[2], la[3]);
                mma16816(S[nb], qh[2][0], qh[2][1], qh[2][2], qh[2][3], lb[0], lb[1]);
                mma16816(S[nb], qh[3][0], qh[3][1], qh[3][2], qh[3][3], lb[2], lb[3]);
                mma16816(S[nb], ql[0][0], ql[0][1], ql[0][2], ql[0][3], ka[0], ka[1]);
                mma16816(S[nb], ql[1][0], ql[1][1], ql[1][2], ql[1][3], ka[2], ka[3]);
                mma16816(S[nb], ql[2][0], ql[2][1], ql[2][2], ql[2][3], kb_[0], kb_[1]);
                mma16816(S[nb], ql[3][0], ql[3][1], ql[3][2], ql[3][3], kb_[2], kb_[3]);
            }

            // ---- scale + causal mask ----
            if (kt*64 + 63 > qb + wid*16) {
                #pragma unroll
                for (int nb = 0; nb < 8; nb++) {
                    const int cg = kt*64 + nb*8 + lr*2;
                    S[nb][0] = (cg     > rg0    ) ? -1e30f : S[nb][0] * 0.125f;
                    S[nb][1] = (cg + 1 > rg0    ) ? -1e30f : S[nb][1] * 0.125f;
                    S[nb][2] = (cg     > rg0 + 8) ? -1e30f : S[nb][2] * 0.125f;
                    S[nb][3] = (cg + 1 > rg0 + 8) ? -1e30f : S[nb][3] * 0.125f;
                }
            } else {
                #pragma unroll
                for (int nb = 0; nb < 8; nb++)
                    #pragma unroll
                    for (int c = 0; c < 4; c++) S[nb][c] *= 0.125f;
            }

            // ---- online softmax (rows rg0, rg0+8) ----
            float mx0 = -1e30f, mx1 = -1e30f;
            #pragma unroll
            for (int nb = 0; nb < 8; nb++) {
                mx0 = fmaxf(mx0, fmaxf(S[nb][0], S[nb][1]));
                mx1 = fmaxf(mx1, fmaxf(S[nb][2], S[nb][3]));
            }
            mx0 = fmaxf(mx0, __shfl_xor_sync(0xffffffffu, mx0, 1));
            mx0 = fmaxf(mx0, __shfl_xor_sync(0xffffffffu, mx0, 2));
            mx1 = fmaxf(mx1, __shfl_xor_sync(0xffffffffu, mx1, 1));
            mx1 = fmaxf(mx1, __shfl_xor_sync(0xffffffffu, mx1, 2));
            const float mn0 = fmaxf(m0, mx0), mn1 = fmaxf(m1, mx1);
            const float al0 = __expf(m0 - mn0), al1 = __expf(m1 - mn1);
            float s0 = 0.f, s1 = 0.f;
            #pragma unroll
            for (int nb = 0; nb < 8; nb++) {
                S[nb][0] = __expf(S[nb][0] - mn0); s0 += S[nb][0];
                S[nb][1] = __expf(S[nb][1] - mn0); s0 += S[nb][1];
                S[nb][2] = __expf(S[nb][2] - mn1); s1 += S[nb][2];
                S[nb][3] = __expf(S[nb][3] - mn1); s1 += S[nb][3];
            }
            s0 += __shfl_xor_sync(0xffffffffu, s0, 1);
            s0 += __shfl_xor_sync(0xffffffffu, s0, 2);
            s1 += __shfl_xor_sync(0xffffffffu, s1, 1);
            s1 += __shfl_xor_sync(0xffffffffu, s1, 2);
            l0 = l0*al0 + s0; l1 = l1*al1 + s1;
            m0 = mn0; m1 = mn1;
            #pragma unroll
            for (int i = 0; i < 8; i++) {
                O[i][0] *= al0; O[i][1] *= al0;
                O[i][2] *= al1; O[i][3] *= al1;
            }

            // ---- P fragments from S accumulators (register repack, split) ----
            uint32_t ph[4][4], pl[4][4];
            #pragma unroll
            for (int kb = 0; kb < 4; kb++) {
                const int nA = 2*kb, nBd = 2*kb + 1;
                ph[kb][0] = packbf(S[nA][0],  S[nA][1]);
                ph[kb][1] = packbf(S[nA][2],  S[nA][3]);
                ph[kb][2] = packbf(S[nBd][0], S[nBd][1]);
                ph[kb][3] = packbf(S[nBd][2], S[nBd][3]);
                pl[kb][0] = packbf(S[nA][0]  - bfx2_lo(ph[kb][0]), S[nA][1]  - bfx2_hi(ph[kb][0]));
                pl[kb][1] = packbf(S[nA][2]  - bfx2_lo(ph[kb][1]), S[nA][3]  - bfx2_hi(ph[kb][1]));
                pl[kb][2] = packbf(S[nBd][0] - bfx2_lo(ph[kb][2]), S[nBd][1] - bfx2_hi(ph[kb][2]));
                pl[kb][3] = packbf(S[nBd][2] - bfx2_lo(ph[kb][3]), S[nBd][3] - bfx2_hi(ph[kb][3]));
            }

            // ---- O += P V (3-term split) ----
            #pragma unroll
            for (int no = 0; no < 8; no++) {
                uint32_t va[4], vb[4], wa[4], wb[4];
                const uint32_t ro = (uint32_t)(no * 8 * 128);
                ldsm_x4(va[0], va[1], va[2], va[3], sb + 2*AT_TILE_B + ro + off1);
                ldsm_x4(vb[0], vb[1], vb[2], vb[3], sb + 2*AT_TILE_B + ro + off2);
                ldsm_x4(wa[0], wa[1], wa[2], wa[3], sb + 3*AT_TILE_B + ro + off1);
                ldsm_x4(wb[0], wb[1], wb[2], wb[3], sb + 3*AT_TILE_B + ro + off2);
                mma16816(O[no], ph[0][0], ph[0][1], ph[0][2], ph[0][3], va[0], va[1]);
                mma16816(O[no], ph[1][0], ph[1][1], ph[1][2], ph[1][3], va[2], va[3]);
                mma16816(O[no], ph[2][0], ph[2][1], ph[2][2], ph[2][3], vb[0], vb[1]);
                mma16816(O[no], ph[3][0], ph[3][1], ph[3][2], ph[3][3], vb[2], vb[3]);
                mma16816(O[no], ph[0][0], ph[0][1], ph[0][2], ph[0][3], wa[0], wa[1]);
                mma16816(O[no], ph[1][0], ph[1][1], ph[1][2], ph[1][3], wa[2], wa[3]);
                mma16816(O[no], ph[2][0], ph[2][1], ph[2][2], ph[2][3], wb[0], wb[1]);
                mma16816(O[no], ph[3][0], ph[3][1], ph[3][2], ph[3][3], wb[2], wb[3]);
                mma16816(O[no], pl[0][0], pl[0][1], pl[0][2], pl[0][3], va[0], va[1]);
                mma16816(O[no], pl[1][0], pl[1][1], pl[1][2], pl[1][3], va[2], va[3]);
                mma16816(O[no], pl[2][0], pl[2][1], pl[2][2], pl[2][3], vb[0], vb[1]);
                mma16816(O[no], pl[3][0], pl[3][1], pl[3][2], pl[3][3], vb[2], vb[3]);
            }
        }
        __syncthreads();
    }

    // ---- epilogue: normalize and write [b,t,d] ----
    const int bi = bh >> 4, h = bh & 15;
    const int t0 = qb + wid*16 + lq;
    const float i0 = 1.f / l0, i1 = 1.f / l1;
    #pragma unroll
    for (int no = 0; no < 8; no++) {
        const int dh = no*8 + lr*2;
        float2 u; u.x = O[no][0]*i0; u.y = O[no][1]*i0;
        *(float2*)&g_att[((size_t)(bi*NT + t0))*ND + h*64 + dh] = u;
        float2 w; w.x = O[no][2]*i1; w.y = O[no][3]*i1;
        *(float2*)&g_att[((size_t)(bi*NT + t0 + 8))*ND + h*64 + dh] = w;
    }
}

// ---------------------------------------------------------------------------
// Launch. Inputs: x, mask, wq, bq, wk, bk, wv, bv, wo, bo.
// ---------------------------------------------------------------------------
extern "C" void kernel_launch(void* const* d_in, const int* in_sizes, int n_in,
                              void* d_out, int out_size)
{
    const float* x  = (const float*)d_in[0];
    const float* wq = (const float*)d_in[2];
    const float* bq = (const float*)d_in[3];
    const float* wk = (const float*)d_in[4];
    const float* bk = (const float*)d_in[5];
    const float* wv = (const float*)d_in[6];
    const float* bv = (const float*)d_in[7];
    const float* wo = (const float*)d_in[8];
    const float* bo = (const float*)d_in[9];
    float* out = (float*)d_out;

    __nv_bfloat16 *xhi, *xlo; float* attp;
    cudaGetSymbolAddress((void**)&xhi, g_xhi);
    cudaGetSymbolAddress((void**)&xlo, g_xlo);
    cudaGetSymbolAddress((void**)&attp, g_att);

    cudaFuncSetAttribute(hmma_gemm<0>,
                         cudaFuncAttributeMaxDynamicSharedMemorySize, SMEM_GEMM);
    cudaFuncSetAttribute(hmma_gemm<1>,
                         cudaFuncAttributeMaxDynamicSharedMemorySize, SMEM_GEMM);
    cudaFuncSetAttribute(attn_hmma,
                         cudaFuncAttributeMaxDynamicSharedMemorySize, SMEM_ATTN);

    // 1) split x; transpose+split weights; rope trig table
    split_kernel<<<(MTOT*ND)/256, 256>>>(x, xhi, xlo, MTOT*ND);
    wsplit_kernel<<<dim3(32, 32, 4), dim3(32, 8)>>>(wq, wk, wv, wo);
    rope_table<<<(NT*32)/256, 256>>>();

    // 2) fused QKV projections -> g_q/g_k/g_v fp32 [b,h,t,dh]
    hmma_gemm<0><<<dim3(8, 32, 3), 256, SMEM_GEMM>>>(xhi, xlo, bq, bk, bv, nullptr);

    // 3) RoPE + split Q,K -> bf16 hi/lo; transpose+split V
    rope_apply<<<(NB*NH*NT*32)/256, 256>>>();
    vtrans<<<dim3(NT/64, NB*NH), 256>>>();

    // 4) HMMA flash attention -> g_att [b,t,d]
    attn_hmma<<<dim3(NT/128, NB*NH), 256, SMEM_ATTN>>>();

    // 5) split attention output; out-projection
    split_kernel<<<(MTOT*ND)/256, 256>>>(attp, xhi, xlo, MTOT*ND);
    hmma_gemm<1><<<dim3(8, 32, 1), 256, SMEM_GEMM>>>(xhi, xlo, bo, bo, bo, out);
}

// round 6
// speedup vs baseline: 3.0078x; 1.1178x over previous
#include <cuda_runtime.h>
#include <cuda_bf16.h>
#include <cstdint>

#define NB 2
#define NT 2048
#define ND 1024
#define NH 16
#define NDH 64
#define MTOT (NB*NT)   // 4096

// ---------------------------------------------------------------------------
// Scratch (__device__ globals; allocation-free rule)
// ---------------------------------------------------------------------------
__device__ float g_v[NB*NH*NT*NDH];             // [b,h,t,dh] fp32 (pre-transpose)

__device__ __nv_bfloat16 g_xhi[MTOT*ND];        // split activations (x, then attn out)
__device__ __nv_bfloat16 g_xlo[MTOT*ND];
__device__ __nv_bfloat16 g_wthi[4*ND*ND];       // transposed split weights [z][n][k]
__device__ __nv_bfloat16 g_wtlo[4*ND*ND];

// post-rope split operands for attention
__device__ __nv_bfloat16 g_qhi[NB*NH*NT*NDH];   // [b,h,t,dh]
__device__ __nv_bfloat16 g_qlo[NB*NH*NT*NDH];
__device__ __nv_bfloat16 g_khi[NB*NH*NT*NDH];
__device__ __nv_bfloat16 g_klo[NB*NH*NT*NDH];
__device__ __nv_bfloat16 g_vthi[NB*NH*NT*NDH];  // [b,h,dh,t]  (transposed)
__device__ __nv_bfloat16 g_vtlo[NB*NH*NT*NDH];

__device__ float4 g_rope[NT*32];                // (c1,s1,c2,s2) per (t,j)

// ---------------------------------------------------------------------------
// PTX helpers: base-target-safe (mma.sync / cp.async / ldmatrix; NO tcgen05)
// ---------------------------------------------------------------------------
__device__ __forceinline__ uint32_t smem_u32(const void* p) {
    uint32_t a;
    asm("{ .reg .u64 t; cvta.to.shared.u64 t, %1; cvt.u32.u64 %0, t; }"
        : "=r"(a) : "l"(p));
    return a;
}
#define CP_ASYNC16(saddr, gptr) \
    asm volatile("cp.async.cg.shared.global [%0], [%1], 16;" \
                 :: "r"(saddr), "l"(gptr) : "memory")
#define CP_COMMIT() asm volatile("cp.async.commit_group;" ::: "memory")
template<int N>
__device__ __forceinline__ void cp_wait() {
    asm volatile("cp.async.wait_group %0;" :: "n"(N) : "memory");
}
__device__ __forceinline__ void mma16816(float* d,
        uint32_t a0, uint32_t a1, uint32_t a2, uint32_t a3,
        uint32_t b0, uint32_t b1) {
    asm volatile(
        "mma.sync.aligned.m16n8k16.row.col.f32.bf16.bf16.f32 "
        "{%0,%1,%2,%3}, {%4,%5,%6,%7}, {%8,%9}, {%0,%1,%2,%3};"
        : "+f"(d[0]), "+f"(d[1]), "+f"(d[2]), "+f"(d[3])
        : "r"(a0), "r"(a1), "r"(a2), "r"(a3), "r"(b0), "r"(b1));
}
__device__ __forceinline__ void ldsm_x4(uint32_t& r0, uint32_t& r1,
                                        uint32_t& r2, uint32_t& r3, uint32_t addr) {
    asm volatile("ldmatrix.sync.aligned.m8n8.x4.shared.b16 {%0,%1,%2,%3}, [%4];"
                 : "=r"(r0), "=r"(r1), "=r"(r2), "=r"(r3) : "r"(addr));
}
__device__ __forceinline__ uint32_t lds32(const char* base, int elem) {
    return *(const uint32_t*)(base + elem * 2);
}
__device__ __forceinline__ uint32_t packbf(float lo, float hi) {
    uint32_t d;
    asm("cvt.rn.bf16x2.f32 %0, %1, %2;" : "=r"(d) : "f"(hi), "f"(lo));
    return d;
}
__device__ __forceinline__ float bfx2_lo(uint32_t u) { return __uint_as_float(u << 16); }
__device__ __forceinline__ float bfx2_hi(uint32_t u) { return __uint_as_float(u & 0xffff0000u); }

#define SWZ128(o) ((o) ^ (((o) >> 3) & 0x70))

// ---------------------------------------------------------------------------
// Split fp32 -> bf16 hi/lo (only used for the input x now)
// ---------------------------------------------------------------------------
__global__ void split_kernel(const float* __restrict__ src,
                             __nv_bfloat16* __restrict__ hi,
                             __nv_bfloat16* __restrict__ lo, int n)
{
    int i = blockIdx.x * blockDim.x + threadIdx.x;
    if (i < n) {
        float v = src[i];
        __nv_bfloat16 h = __float2bfloat16(v);
        hi[i] = h;
        lo[i] = __float2bfloat16(v - __bfloat162float(h));
    }
}

// ---------------------------------------------------------------------------
// Transpose + split all 4 weights: W[k][n] -> T[z][n][k] (hi/lo bf16)
// ---------------------------------------------------------------------------
__global__ void wsplit_kernel(const float* __restrict__ w0, const float* __restrict__ w1,
                              const float* __restrict__ w2, const float* __restrict__ w3)
{
    __shared__ float tile[32][33];
    int z = blockIdx.z;
    const float* W = (z == 0) ? w0 : (z == 1) ? w1 : (z == 2) ? w2 : w3;
    int k0 = blockIdx.y * 32, n0 = blockIdx.x * 32;
    int tx = threadIdx.x, ty = threadIdx.y;
    #pragma unroll
    for (int i = 0; i < 4; i++)
        tile[ty + i*8][tx] = W[(k0 + ty + i*8) * ND + n0 + tx];
    __syncthreads();
    #pragma unroll
    for (int i = 0; i < 4; i++) {
        float v = tile[tx][ty + i*8];
        __nv_bfloat16 h = __float2bfloat16(v);
        int idx = z*ND*ND + (n0 + ty + i*8) * ND + (k0 + tx);
        g_wthi[idx] = h;
        g_wtlo[idx] = __float2bfloat16(v - __bfloat162float(h));
    }
}

// ---------------------------------------------------------------------------
// RoPE trig table (dp evals hoisted: 65K instead of 4.2M)
// ---------------------------------------------------------------------------
__global__ void rope_table()
{
    int idx = blockIdx.x * blockDim.x + threadIdx.x;
    if (idx >= NT*32) return;
    int t = idx >> 5, j = idx & 31;
    const double LN1E4 = 9.210340371976184;
    double e1 = (double)(j & ~1) / 64.0;
    double e2 = (double)((j & ~1) + 32) / 64.0;
    double a1 = (double)t * exp(-e1 * LN1E4);
    double a2 = (double)t * exp(-e2 * LN1E4);
    float4 r;
    r.x = (float)cos(a1); r.y = (float)sin(a1);
    r.z = (float)cos(a2); r.w = (float)sin(a2);
    g_rope[idx] = r;
}

// ---------------------------------------------------------------------------
// HMMA split-bf16 GEMM: C[4096,1024] = X @ W + bias
// BK=32, double-buffered (81920 B smem) -> 2 CTAs/SM (16 warps).
// MODE 0: z=0/1 -> fused RoPE + split -> g_q/g_k hi,lo bf16 [b,h,t,dh]
//         z=2   -> g_v fp32 [b,h,t,dh]
// MODE 1: z=3 (wo) -> OutP fp32 [b,t,d]
// ---------------------------------------------------------------------------
#define BK 32
#define STRIDE 40                       // 32 + 8 pad (conflict-free lds32)
#define TILE_B (128*STRIDE*2)           // 10240 B
#define BUF_B  (4*TILE_B)               // 40960 B
#define SMEM_GEMM (2*BUF_B)             // 81920 B

template<int MODE>
__global__ __launch_bounds__(256, 2)
void hmma_gemm(const __nv_bfloat16* __restrict__ Ahi_g,
               const __nv_bfloat16* __restrict__ Alo_g,
               const float* __restrict__ b0, const float* __restrict__ b1,
               const float* __restrict__ b2,
               float* __restrict__ OutP)
{
    extern __shared__ __align__(16) char smem[];
    const int tid = threadIdx.x;
    const int wid = tid >> 5;
    const int lane = tid & 31;
    const int lq = lane >> 2;
    const int lr = lane & 3;

    const int z = (MODE == 0) ? blockIdx.z : 3;
    const __nv_bfloat16* Bhi_g = g_wthi + (size_t)z * ND * ND;
    const __nv_bfloat16* Blo_g = g_wtlo + (size_t)z * ND * ND;
    const float* bias = (MODE == 0) ? ((z == 0) ? b0 : (z == 1) ? b1 : b2) : b0;

    const int m0 = blockIdx.y * 128, n0 = blockIdx.x * 128;
    const int wm = (wid >> 1) * 32;
    const int wn = (wid & 1) * 64;

    // loader: 2 threads/row, 32 B each
    const int lrow = tid >> 1, lhalf = tid & 1;
    const __nv_bfloat16* gA_hi = Ahi_g + (size_t)(m0 + lrow) * ND + lhalf * 16;
    const __nv_bfloat16* gA_lo = Alo_g + (size_t)(m0 + lrow) * ND + lhalf * 16;
    const __nv_bfloat16* gB_hi = Bhi_g + (size_t)(n0 + lrow) * ND + lhalf * 16;
    const __nv_bfloat16* gB_lo = Blo_g + (size_t)(n0 + lrow) * ND + lhalf * 16;
    const uint32_t sldst = smem_u32(smem) + (lrow * STRIDE + lhalf * 16) * 2;

    float acc[2][8][4];
    #pragma unroll
    for (int mt = 0; mt < 2; mt++)
        #pragma unroll
        for (int nt = 0; nt < 8; nt++)
            #pragma unroll
            for (int i = 0; i < 4; i++) acc[mt][nt][i] = 0.f;

    auto issue = [&](int chunk, int buf) {
        const uint32_t s = sldst + buf * BUF_B;
        const int g = chunk * BK;
        #pragma unroll
        for (int i = 0; i < 2; i++) {
            CP_ASYNC16(s + 0*TILE_B + i*16, gA_hi + g + i*8);
            CP_ASYNC16(s + 1*TILE_B + i*16, gA_lo + g + i*8);
            CP_ASYNC16(s + 2*TILE_B + i*16, gB_hi + g + i*8);
            CP_ASYNC16(s + 3*TILE_B + i*16, gB_lo + g + i*8);
        }
        CP_COMMIT();
    };

    issue(0, 0);
    issue(1, 1);

    const int NCHUNK = ND / BK;             // 32
    for (int c = 0; c < NCHUNK; c++) {
        const int buf = c & 1;
        if (c < NCHUNK - 1) cp_wait<1>(); else cp_wait<0>();
        __syncthreads();

        const char* base = smem + buf * BUF_B;
        const char* sAh = base;
        const char* sAl = base + 1*TILE_B;
        const char* sBh = base + 2*TILE_B;
        const char* sBl = base + 3*TILE_B;

        #pragma unroll
        for (int ks = 0; ks < 2; ks++) {
            const int kc = ks * 16 + lr * 2;
            uint32_t ah[2][4], al[2][4];
            #pragma unroll
            for (int mt = 0; mt < 2; mt++) {
                const int r0 = wm + mt * 16 + lq;
                ah[mt][0] = lds32(sAh, r0*STRIDE + kc);
                ah[mt][1] = lds32(sAh, (r0+8)*STRIDE + kc);
                ah[mt][2] = lds32(sAh, r0*STRIDE + kc + 8);
                ah[mt][3] = lds32(sAh, (r0+8)*STRIDE + kc + 8);
                al[mt][0] = lds32(sAl, r0*STRIDE + kc);
                al[mt][1] = lds32(sAl, (r0+8)*STRIDE + kc);
                al[mt][2] = lds32(sAl, r0*STRIDE + kc + 8);
                al[mt][3] = lds32(sAl, (r0+8)*STRIDE + kc + 8);
            }
            #pragma unroll
            for (int nt = 0; nt < 8; nt++) {
                const int nr = wn + nt * 8 + lq;
                uint32_t bh0 = lds32(sBh, nr*STRIDE + kc);
                uint32_t bh1 = lds32(sBh, nr*STRIDE + kc + 8);
                uint32_t bl0 = lds32(sBl, nr*STRIDE + kc);
                uint32_t bl1 = lds32(sBl, nr*STRIDE + kc + 8);
                #pragma unroll
                for (int mt = 0; mt < 2; mt++) {
                    mma16816(acc[mt][nt], ah[mt][0], ah[mt][1], ah[mt][2], ah[mt][3], bh0, bh1);
                    mma16816(acc[mt][nt], ah[mt][0], ah[mt][1], ah[mt][2], ah[mt][3], bl0, bl1);
                    mma16816(acc[mt][nt], al[mt][0], al[mt][1], al[mt][2], al[mt][3], bh0, bh1);
                }
            }
        }
        __syncthreads();
        if (c + 2 < NCHUNK) issue(c + 2, buf);
    }

    // ------------------------- epilogue -------------------------
    const int nh0 = (n0 + wn) >> 6;     // head index (warp spans one 64-col head)
    if (MODE == 1) {
        #pragma unroll
        for (int mt = 0; mt < 2; mt++)
            #pragma unroll
            for (int nt = 0; nt < 8; nt++) {
                const int n = n0 + wn + nt * 8 + lr * 2;
                const float bx = bias[n], by = bias[n + 1];
                const int row0 = m0 + wm + mt * 16 + lq;
                #pragma unroll
                for (int half = 0; half < 2; half++) {
                    const int m = row0 + half * 8;
                    float2 v;
                    v.x = acc[mt][nt][half*2 + 0] + bx;
                    v.y = acc[mt][nt][half*2 + 1] + by;
                    *(float2*)&OutP[(size_t)m * ND + n] = v;
                }
            }
    } else if (z == 2) {
        // V: plain fp32 [b,h,t,dh]
        #pragma unroll
        for (int mt = 0; mt < 2; mt++)
            #pragma unroll
            for (int nt = 0; nt < 8; nt++) {
                const int n = n0 + wn + nt * 8 + lr * 2;
                const float bx = bias[n], by = bias[n + 1];
                const int row0 = m0 + wm + mt * 16 + lq;
                #pragma unroll
                for (int half = 0; half < 2; half++) {
                    const int m = row0 + half * 8;
                    const int bi = m >> 11, t = m & (NT - 1);
                    float2 v;
                    v.x = acc[mt][nt][half*2 + 0] + bx;
                    v.y = acc[mt][nt][half*2 + 1] + by;
                    *(float2*)&g_v[(((size_t)(bi*NH + nh0)*NT + t) << 6) + (n & 63)] = v;
                }
            }
    } else {
        // Q or K: fused RoPE + hi/lo split (register-local: cols j and j+32
        // live in acc[mt][nt] and acc[mt][nt+4] of the same thread)
        __nv_bfloat16* dhi = (z == 0) ? g_qhi : g_khi;
        __nv_bfloat16* dlo = (z == 0) ? g_qlo : g_klo;
        #pragma unroll
        for (int mt = 0; mt < 2; mt++)
            #pragma unroll
            for (int half = 0; half < 2; half++) {
                const int m = m0 + wm + mt * 16 + lq + half * 8;
                const int bi = m >> 11, t = m & (NT - 1);
                __nv_bfloat16* rh = dhi + (((size_t)(bi*NH + nh0)*NT + t) << 6);
                __nv_bfloat16* rl = dlo + (((size_t)(bi*NH + nh0)*NT + t) << 6);
                #pragma unroll
                for (int nt = 0; nt < 4; nt++) {
                    const int j = nt * 8 + lr * 2;           // < 32
                    const int n = n0 + wn + j;
                    float r1[2], r2[2];
                    #pragma unroll
                    for (int e = 0; e < 2; e++) {
                        float a1 = acc[mt][nt][half*2 + e]     + bias[n + e];
                        float a2 = acc[mt][nt + 4][half*2 + e] + bias[n + 32 + e];
                        float4 cs = g_rope[t*32 + j + e];
                        r1[e] = a1*cs.x - a2*cs.y;
                        r2[e] = a2*cs.z + a1*cs.w;
                    }
                    uint32_t h1 = packbf(r1[0], r1[1]);
                    uint32_t h2 = packbf(r2[0], r2[1]);
                    uint32_t l1 = packbf(r1[0] - bfx2_lo(h1), r1[1] - bfx2_hi(h1));
                    uint32_t l2 = packbf(r2[0] - bfx2_lo(h2), r2[1] - bfx2_hi(h2));
                    *(uint32_t*)(rh + j)      = h1;
                    *(uint32_t*)(rh + j + 32) = h2;
                    *(uint32_t*)(rl + j)      = l1;
                    *(uint32_t*)(rl + j + 32) = l2;
                }
            }
    }
}

// ---------------------------------------------------------------------------
// V transpose + split: g_v [b,h,t,dh] fp32 -> g_vthi/lo [b,h,dh,t] bf16
// ---------------------------------------------------------------------------
__global__ __launch_bounds__(256) void vtrans()
{
    __shared__ float tile[64][65];
    const int bh = blockIdx.y, tb = blockIdx.x * 64;
    const int tid = threadIdx.x;
    const int r = tid >> 2, c4 = (tid & 3) * 16;
    const float* src = g_v + ((size_t)bh*NT + tb + r) * 64 + c4;
    #pragma unroll
    for (int i = 0; i < 4; i++) {
        float4 v = *(const float4*)(src + i*4);
        tile[r][c4+i*4+0] = v.x; tile[r][c4+i*4+1] = v.y;
        tile[r][c4+i*4+2] = v.z; tile[r][c4+i*4+3] = v.w;
    }
    __syncthreads();
    const int dh = tid >> 2, t4 = (tid & 3) * 16;
    size_t ob = ((size_t)bh*64 + dh) * NT + tb + t4;
    #pragma unroll
    for (int i = 0; i < 8; i++) {
        float a = tile[t4 + 2*i][dh], b = tile[t4 + 2*i + 1][dh];
        __nv_bfloat16 ha = __float2bfloat16(a), hb = __float2bfloat16(b);
        *(__nv_bfloat162*)(g_vthi + ob + 2*i) = __nv_bfloat162(ha, hb);
        __nv_bfloat16 la = __float2bfloat16(a - __bfloat162float(ha));
        __nv_bfloat16 lb = __float2bfloat16(b - __bfloat162float(hb));
        *(__nv_bfloat162*)(g_vtlo + ob + 2*i) = __nv_bfloat162(la, lb);
    }
}

// ---------------------------------------------------------------------------
// HMMA flash attention, split-bf16 3-term, causal.
// BM=128 (8 warps x 16 rows), BN=64 keys/tile, double-buffered cp.async smem.
// Epilogue writes split bf16 directly into g_xhi/g_xlo (feeds out-proj GEMM).
// ---------------------------------------------------------------------------
#define AT_TILE_B 8192              // 64 rows x 128 B
#define AT_BUF_B  (4*AT_TILE_B)     // Khi,Klo,Vthi,Vtlo
#define SMEM_ATTN (2*AT_BUF_B)      // 65536

__global__ __launch_bounds__(256)
void attn_hmma()
{
    extern __shared__ __align__(128) char asmem[];
    const uint32_t sbase = smem_u32(asmem);
    const int tid = threadIdx.x, wid = tid >> 5, lane = tid & 31;
    const int lq = lane >> 2, lr = lane & 3;
    const int bx = gridDim.x - 1 - blockIdx.x;     // big-work CTAs first
    const int bh = blockIdx.y;
    const int qb = bx * 128;
    const int last = 2*bx + 1;

    const size_t hb = (size_t)bh * NT * 64;
    const __nv_bfloat16* Qh = g_qhi + hb;
    const __nv_bfloat16* Ql = g_qlo + hb;
    const __nv_bfloat16* Kh = g_khi + hb;
    const __nv_bfloat16* Kl = g_klo + hb;
    const __nv_bfloat16* Vh = g_vthi + hb;   // [dh][t]
    const __nv_bfloat16* Vl = g_vtlo + hb;

    uint32_t qh[4][4], ql[4][4];
    {
        const size_t r0 = (size_t)(qb + wid*16 + lq);
        #pragma unroll
        for (int kb = 0; kb < 4; kb++) {
            const int d0 = kb*16 + lr*2;
            qh[kb][0] = *(const uint32_t*)(Qh + r0*64 + d0);
            qh[kb][1] = *(const uint32_t*)(Qh + (r0+8)*64 + d0);
            qh[kb][2] = *(const uint32_t*)(Qh + r0*64 + d0 + 8);
            qh[kb][3] = *(const uint32_t*)(Qh + (r0+8)*64 + d0 + 8);
            ql[kb][0] = *(const uint32_t*)(Ql + r0*64 + d0);
            ql[kb][1] = *(const uint32_t*)(Ql + (r0+8)*64 + d0);
            ql[kb][2] = *(const uint32_t*)(Ql + r0*64 + d0 + 8);
            ql[kb][3] = *(const uint32_t*)(Ql + (r0+8)*64 + d0 + 8);
        }
    }

    float O[8][4];
    #pragma unroll
    for (int i = 0; i < 8; i++)
        #pragma unroll
        for (int c = 0; c < 4; c++) O[i][c] = 0.f;
    float m0 = -1e30f, m1 = -1e30f, l0 = 0.f, l1 = 0.f;

    const int lrow = tid >> 2;
    const int lcb  = (tid & 3) * 2;

    auto issue = [&](int kt, int buf) {
        const uint32_t sb = sbase + buf * AT_BUF_B;
        #pragma unroll
        for (int c2 = 0; c2 < 2; c2++) {
            const int c = lcb + c2;
            const uint32_t sw = SWZ128((uint32_t)(lrow*128 + c*16));
            const size_t gk = ((size_t)(kt*64 + lrow))*64 + c*8;
            const size_t gv = (size_t)lrow*NT + kt*64 + c*8;
            CP_ASYNC16(sb + 0*AT_TILE_B + sw, Kh + gk);
            CP_ASYNC16(sb + 1*AT_TILE_B + sw, Kl + gk);
            CP_ASYNC16(sb + 2*AT_TILE_B + sw, Vh + gv);
            CP_ASYNC16(sb + 3*AT_TILE_B + sw, Vl + gv);
        }
        CP_COMMIT();
    };

    issue(0, 0);
    const int rg0 = qb + wid*16 + lq;
    const int trow = lane & 7;
    const int tcol = (lane >> 3) * 16;

    for (int kt = 0; kt <= last; kt++) {
        if (kt < last) issue(kt + 1, (kt + 1) & 1);
        if (kt < last) cp_wait<1>(); else cp_wait<0>();
        __syncthreads();

        const bool active = (kt*64 <= qb + wid*16 + 15);
        if (active) {
            const uint32_t sb = sbase + (kt & 1) * AT_BUF_B;
            const uint32_t off1 = SWZ128((uint32_t)(trow*128 + tcol));
            const uint32_t off2 = SWZ128((uint32_t)(trow*128 + 64 + tcol));

            float S[8][4];
            #pragma unroll
            for (int nb = 0; nb < 8; nb++) {
                uint32_t ka[4], kb_[4], la[4], lb[4];
                const uint32_t ro = (uint32_t)(nb * 8 * 128);
                ldsm_x4(ka[0], ka[1], ka[2], ka[3], sb + 0*AT_TILE_B + ro + off1);
                ldsm_x4(kb_[0], kb_[1], kb_[2], kb_[3], sb + 0*AT_TILE_B + ro + off2);
                ldsm_x4(la[0], la[1], la[2], la[3], sb + 1*AT_TILE_B + ro + off1);
                ldsm_x4(lb[0], lb[1], lb[2], lb[3], sb + 1*AT_TILE_B + ro + off2);
                S[nb][0] = S[nb][1] = S[nb][2] = S[nb][3] = 0.f;
                mma16816(S[nb], qh[0][0], qh[0][1], qh[0][2], qh[0][3], ka[0], ka[1]);
                mma16816(S[nb], qh[1][0], qh[1][1], qh[1][2], qh[1][3], ka[2], ka[3]);
                mma16816(S[nb], qh[2][0], qh[2][1], qh[2][2], qh[2][3], kb_[0], kb_[1]);
                mma16816(S[nb], qh[3][0], qh[3][1], qh[3][2], qh[3][3], kb_[2], kb_[3]);
                mma16816(S[nb], qh[0][0], qh[0][1], qh[0][2], qh[0][3], la[0], la[1]);
                mma16816(S[nb], qh[1][0], qh[1][1], qh[1][2], qh[1][3], la[2], la[3]);
                mma16816(S[nb], qh[2][0], qh[2][1], qh[2][2], qh[2][3], lb[0], lb[1]);
                mma16816(S[nb], qh[3][0], qh[3][1], qh[3][2], qh[3][3], lb[2], lb[3]);
                mma16816(S[nb], ql[0][0], ql[0][1], ql[0][2], ql[0][3], ka[0], ka[1]);
                mma16816(S[nb], ql[1][0], ql[1][1], ql[1][2], ql[1][3], ka[2], ka[3]);
                mma16816(S[nb], ql[2][0], ql[2][1], ql[2][2], ql[2][3], kb_[0], kb_[1]);
                mma16816(S[nb], ql[3][0], ql[3][1], ql[3][2], ql[3][3], kb_[2], kb_[3]);
            }

            if (kt*64 + 63 > qb + wid*16) {
                #pragma unroll
                for (int nb = 0; nb < 8; nb++) {
                    const int cg = kt*64 + nb*8 + lr*2;
                    S[nb][0] = (cg     > rg0    ) ? -1e30f : S[nb][0] * 0.125f;
                    S[nb][1] = (cg + 1 > rg0    ) ? -1e30f : S[nb][1] * 0.125f;
                    S[nb][2] = (cg     > rg0 + 8) ? -1e30f : S[nb][2] * 0.125f;
                    S[nb][3] = (cg + 1 > rg0 + 8) ? -1e30f : S[nb][3] * 0.125f;
                }
            } else {
                #pragma unroll
                for (int nb = 0; nb < 8; nb++)
                    #pragma unroll
                    for (int c = 0; c < 4; c++) S[nb][c] *= 0.125f;
            }

            float mx0 = -1e30f, mx1 = -1e30f;
            #pragma unroll
            for (int nb = 0; nb < 8; nb++) {
                mx0 = fmaxf(mx0, fmaxf(S[nb][0], S[nb][1]));
                mx1 = fmaxf(mx1, fmaxf(S[nb][2], S[nb][3]));
            }
            mx0 = fmaxf(mx0, __shfl_xor_sync(0xffffffffu, mx0, 1));
            mx0 = fmaxf(mx0, __shfl_xor_sync(0xffffffffu, mx0, 2));
            mx1 = fmaxf(mx1, __shfl_xor_sync(0xffffffffu, mx1, 1));
            mx1 = fmaxf(mx1, __shfl_xor_sync(0xffffffffu, mx1, 2));
            const float mn0 = fmaxf(m0, mx0), mn1 = fmaxf(m1, mx1);
            const float al0 = __expf(m0 - mn0), al1 = __expf(m1 - mn1);
            float s0 = 0.f, s1 = 0.f;
            #pragma unroll
            for (int nb = 0; nb < 8; nb++) {
                S[nb][0] = __expf(S[nb][0] - mn0); s0 += S[nb][0];
                S[nb][1] = __expf(S[nb][1] - mn0); s0 += S[nb][1];
                S[nb][2] = __expf(S[nb][2] - mn1); s1 += S[nb][2];
                S[nb][3] = __expf(S[nb][3] - mn1); s1 += S[nb][3];
            }
            s0 += __shfl_xor_sync(0xffffffffu, s0, 1);
            s0 += __shfl_xor_sync(0xffffffffu, s0, 2);
            s1 += __shfl_xor_sync(0xffffffffu, s1, 1);
            s1 += __shfl_xor_sync(0xffffffffu, s1, 2);
            l0 = l0*al0 + s0; l1 = l1*al1 + s1;
            m0 = mn0; m1 = mn1;
            #pragma unroll
            for (int i = 0; i < 8; i++) {
                O[i][0] *= al0; O[i][1] *= al0;
                O[i][2] *= al1; O[i][3] *= al1;
            }

            uint32_t ph[4][4], pl[4][4];
            #pragma unroll
            for (int kb = 0; kb < 4; kb++) {
                const int nA = 2*kb, nBd = 2*kb + 1;
                ph[kb][0] = packbf(S[nA][0],  S[nA][1]);
                ph[kb][1] = packbf(S[nA][2],  S[nA][3]);
                ph[kb][2] = packbf(S[nBd][0], S[nBd][1]);
                ph[kb][3] = packbf(S[nBd][2], S[nBd][3]);
                pl[kb][0] = packbf(S[nA][0]  - bfx2_lo(ph[kb][0]), S[nA][1]  - bfx2_hi(ph[kb][0]));
                pl[kb][1] = packbf(S[nA][2]  - bfx2_lo(ph[kb][1]), S[nA][3]  - bfx2_hi(ph[kb][1]));
                pl[kb][2] = packbf(S[nBd][0] - bfx2_lo(ph[kb][2]), S[nBd][1] - bfx2_hi(ph[kb][2]));
                pl[kb][3] = packbf(S[nBd][2] - bfx2_lo(ph[kb][3]), S[nBd][3] - bfx2_hi(ph[kb][3]));
            }

            #pragma unroll
            for (int no = 0; no < 8; no++) {
                uint32_t va[4], vb[4], wa[4], wb[4];
                const uint32_t ro = (uint32_t)(no * 8 * 128);
                ldsm_x4(va[0], va[1], va[2], va[3], sb + 2*AT_TILE_B + ro + off1);
                ldsm_x4(vb[0], vb[1], vb[2], vb[3], sb + 2*AT_TILE_B + ro + off2);
                ldsm_x4(wa[0], wa[1], wa[2], wa[3], sb + 3*AT_TILE_B + ro + off1);
                ldsm_x4(wb[0], wb[1], wb[2], wb[3], sb + 3*AT_TILE_B + ro + off2);
                mma16816(O[no], ph[0][0], ph[0][1], ph[0][2], ph[0][3], va[0], va[1]);
                mma16816(O[no], ph[1][0], ph[1][1], ph[1][2], ph[1][3], va[2], va[3]);
                mma16816(O[no], ph[2][0], ph[2][1], ph[2][2], ph[2][3], vb[0], vb[1]);
                mma16816(O[no], ph[3][0], ph[3][1], ph[3][2], ph[3][3], vb[2], vb[3]);
                mma16816(O[no], ph[0][0], ph[0][1], ph[0][2], ph[0][3], wa[0], wa[1]);
                mma16816(O[no], ph[1][0], ph[1][1], ph[1][2], ph[1][3], wa[2], wa[3]);
                mma16816(O[no], ph[2][0], ph[2][1], ph[2][2], ph[2][3], wb[0], wb[1]);
                mma16816(O[no], ph[3][0], ph[3][1], ph[3][2], ph[3][3], wb[2], wb[3]);
                mma16816(O[no], pl[0][0], pl[0][1], pl[0][2], pl[0][3], va[0], va[1]);
                mma16816(O[no], pl[1][0], pl[1][1], pl[1][2], pl[1][3], va[2], va[3]);
                mma16816(O[no], pl[2][0], pl[2][1], pl[2][2], pl[2][3], vb[0], vb[1]);
                mma16816(O[no], pl[3][0], pl[3][1], pl[3][2], pl[3][3], vb[2], vb[3]);
            }
        }
        __syncthreads();
    }

    // ---- epilogue: normalize + split -> g_xhi/g_xlo [b,t,d] ----
    const int bi = bh >> 4, h = bh & 15;
    const int t0 = qb + wid*16 + lq;
    const float i0 = 1.f / l0, i1 = 1.f / l1;
    #pragma unroll
    for (int no = 0; no < 8; no++) {
        const int dh = no*8 + lr*2;
        const size_t e0 = ((size_t)(bi*NT + t0))*ND + h*64 + dh;
        const size_t e1 = ((size_t)(bi*NT + t0 + 8))*ND + h*64 + dh;
        float ux = O[no][0]*i0, uy = O[no][1]*i0;
        uint32_t hu = packbf(ux, uy);
        uint32_t lu = packbf(ux - bfx2_lo(hu), uy - bfx2_hi(hu));
        *(uint32_t*)(g_xhi + e0) = hu;
        *(uint32_t*)(g_xlo + e0) = lu;
        float wx = O[no][2]*i1, wy = O[no][3]*i1;
        uint32_t hw = packbf(wx, wy);
        uint32_t lw = packbf(wx - bfx2_lo(hw), wy - bfx2_hi(hw));
        *(uint32_t*)(g_xhi + e1) = hw;
        *(uint32_t*)(g_xlo + e1) = lw;
    }
}

// ---------------------------------------------------------------------------
// Launch. Inputs: x, mask, wq, bq, wk, bk, wv, bv, wo, bo.
// ---------------------------------------------------------------------------
extern "C" void kernel_launch(void* const* d_in, const int* in_sizes, int n_in,
                              void* d_out, int out_size)
{
    const float* x  = (const float*)d_in[0];
    const float* wq = (const float*)d_in[2];
    const float* bq = (const float*)d_in[3];
    const float* wk = (const float*)d_in[4];
    const float* bk = (const float*)d_in[5];
    const float* wv = (const float*)d_in[6];
    const float* bv = (const float*)d_in[7];
    const float* wo = (const float*)d_in[8];
    const float* bo = (const float*)d_in[9];
    float* out = (float*)d_out;

    __nv_bfloat16 *xhi, *xlo;
    cudaGetSymbolAddress((void**)&xhi, g_xhi);
    cudaGetSymbolAddress((void**)&xlo, g_xlo);

    cudaFuncSetAttribute(hmma_gemm<0>,
                         cudaFuncAttributeMaxDynamicSharedMemorySize, SMEM_GEMM);
    cudaFuncSetAttribute(hmma_gemm<1>,
                         cudaFuncAttributeMaxDynamicSharedMemorySize, SMEM_GEMM);
    cudaFuncSetAttribute(attn_hmma,
                         cudaFuncAttributeMaxDynamicSharedMemorySize, SMEM_ATTN);

    // 1) split x; transpose+split weights; rope trig table
    split_kernel<<<(MTOT*ND)/256, 256>>>(x, xhi, xlo, MTOT*ND);
    wsplit_kernel<<<dim3(32, 32, 4), dim3(32, 8)>>>(wq, wk, wv, wo);
    rope_table<<<(NT*32)/256, 256>>>();

    // 2) fused QKV projections + RoPE + split (Q,K) / fp32 (V)
    hmma_gemm<0><<<dim3(8, 32, 3), 256, SMEM_GEMM>>>(xhi, xlo, bq, bk, bv, nullptr);

    // 3) transpose+split V
    vtrans<<<dim3(NT/64, NB*NH), 256>>>();

    // 4) HMMA flash attention -> split bf16 in g_xhi/g_xlo
    attn_hmma<<<dim3(NT/128, NB*NH), 256, SMEM_ATTN>>>();

    // 5) out-projection -> d_out
    hmma_gemm<1><<<dim3(8, 32, 1), 256, SMEM_GEMM>>>(xhi, xlo, bo, bo, bo, out);
}